// round 13
// baseline (speedup 1.0000x reference)
#include <cuda_runtime.h>
#include <math.h>
#include <stdint.h>

#define NN     20001
#define NREAL  20000
#define EPAD   1200000
#define RADIUS_F 0.1125f

// ---------------- scratch (device globals; no allocations) ----------------
__device__ float g_B[(size_t)NN * 64 * 96];        // bin accumulator (tf32-rounded), max cin=96
__device__ float g_bufA[(size_t)NN * 96];
__device__ float g_bufB[(size_t)NN * 96];
__device__ float g_inp[(size_t)NN * 96];
__device__ float g_inp2[(size_t)NN * 96];
__device__ float g_y[(size_t)NN * 64];
__device__ float g_ww[(size_t)EPAD * 8];           // win * trilinear weight per corner
__device__ unsigned long long g_kfp[EPAD];         // 8 packed 6-bit kernel indices
__device__ int2 g_ent[(size_t)EPAD * 8];           // (weight bits, dst) sorted by (node,bin)
__device__ int g_boff[NN * 64 + 1];                // per-(node,bin) entry offsets
__device__ float g_w0p[1024 * 64];                 // conv0_w padded cin 13->16
__device__ uint32_t g_Whi[6144 * 64];              // tf32 hi of current layer W
__device__ uint32_t g_Wlo[6144 * 64];              // tf32 lo of current layer W
__device__ int g_rowstart[NN + 2];
__device__ int g_Ereal;

// ---------------- helpers ----------------
__device__ __forceinline__ float fsign(float v) {
    return (v > 0.f) ? 1.f : ((v < 0.f) ? -1.f : 0.f);
}

__device__ __forceinline__ uint32_t f2tf32(float x) {
    uint32_t r;
    asm("cvt.rna.tf32.f32 %0, %1;" : "=r"(r) : "f"(x));
    return r;
}

__device__ __forceinline__ float tf32r(float x) {
    return __uint_as_float(f2tf32(x));
}

__device__ __forceinline__ void mma_tf32(float* d, const uint32_t* a, const uint32_t* b) {
    asm volatile(
        "mma.sync.aligned.m16n8k8.row.col.f32.tf32.tf32.f32 "
        "{%0,%1,%2,%3}, {%4,%5,%6,%7}, {%8,%9}, {%0,%1,%2,%3};"
        : "+f"(d[0]), "+f"(d[1]), "+f"(d[2]), "+f"(d[3])
        : "r"(a[0]), "r"(a[1]), "r"(a[2]), "r"(a[3]), "r"(b[0]), "r"(b[1]));
}

__device__ __forceinline__ void ball_to_cube(float x, float y, float z,
                                             float& a, float& b, float& zc) {
    const float eps = 1e-9f;
    float sq   = x * x + y * y + z * z;
    float norm = sqrtf(sq + eps);
    float rxy2 = x * x + y * y;
    bool  polar = 1.25f * z * z > rxy2;
    float s = polar ? sqrtf(3.f * norm / (norm + fabsf(z) + eps))
                    : norm / sqrtf(rxy2 + eps);
    float xc = x * s;
    float yc = y * s;
    float zz = polar ? fsign(z) * norm : 1.5f * z;
    if (sq < 1e-12f) { xc = 0.f; yc = 0.f; zz = 0.f; }
    float r  = sqrtf(xc * xc + yc * yc + eps);
    bool  c1 = fabsf(xc) >= fabsf(yc);
    float xs = (fabsf(xc) < eps) ? eps : xc;
    float ys = (fabsf(yc) < eps) ? eps : yc;
    const float fop = 1.27323954473516268615f;  // 4/pi
    float av = c1 ? fsign(xc) * r : fsign(yc) * r * fop * atanf(xc / ys);
    float bv = c1 ? fsign(xc) * r * fop * atanf(yc / xs) : fsign(yc) * r;
    if (xc * xc + yc * yc < 1e-12f) { av = 0.f; bv = 0.f; }
    a = av; b = bv; zc = zz;
}

// ---------------- setup kernels ----------------
__global__ void k_findpad(const int* __restrict__ dst) {
    int lo = 0, hi = EPAD;
    while (lo < hi) {
        int mid = (lo + hi) >> 1;
        if (dst[mid] < NREAL) lo = mid + 1; else hi = mid;
    }
    g_Ereal = lo;
    g_boff[NN * 64] = 8 * lo;   // sentinel
}

__global__ void k_rowstart(const int* __restrict__ src) {
    int i = blockIdx.x * blockDim.x + threadIdx.x;
    if (i > NN) return;
    int E = g_Ereal;
    int lo = 0, hi = E;
    while (lo < hi) {
        int mid = (lo + hi) >> 1;
        if (src[mid] < i) lo = mid + 1; else hi = mid;
    }
    g_rowstart[i] = lo;
}

__global__ void k_geom(const float* __restrict__ pos,
                       const int* __restrict__ src,
                       const int* __restrict__ dst) {
    int e = blockIdx.x * blockDim.x + threadIdx.x;
    if (e >= EPAD) return;
    int d = dst[e];
    if (d >= NREAL) return;  // pad edge (win == 0)
    int s = src[e];
    float ox = (pos[(size_t)d * 3 + 0] - pos[(size_t)s * 3 + 0]) * (1.f / RADIUS_F);
    float oy = (pos[(size_t)d * 3 + 1] - pos[(size_t)s * 3 + 1]) * (1.f / RADIUS_F);
    float oz = (pos[(size_t)d * 3 + 2] - pos[(size_t)s * 3 + 2]) * (1.f / RADIUS_F);
    float r2 = ox * ox + oy * oy + oz * oz;
    float u  = 1.f - r2;
    float win = u * u * u;
    win = fminf(fmaxf(win, 0.f), 1.f);
    float ca, cb, cc;
    ball_to_cube(ox, oy, oz, ca, cb, cc);
    float gx = fminf(fmaxf((ca * 0.5f + 0.5f) * 3.f, 0.f), 3.f);
    float gy = fminf(fmaxf((cb * 0.5f + 0.5f) * 3.f, 0.f), 3.f);
    float gz = fminf(fmaxf((cc * 0.5f + 0.5f) * 3.f, 0.f), 3.f);
    float fx = floorf(gx), fy = floorf(gy), fz = floorf(gz);
    float tx = gx - fx, ty = gy - fy, tz = gz - fz;
    int ix0 = min((int)fx, 3), ix1 = min((int)fx + 1, 3);
    int iy0 = min((int)fy, 3), iy1 = min((int)fy + 1, 3);
    int iz0 = min((int)fz, 3), iz1 = min((int)fz + 1, 3);
    unsigned long long kp = 0;
    #pragma unroll
    for (int c = 0; c < 8; c++) {
        int bx = (c >> 2) & 1, by = (c >> 1) & 1, bz = c & 1;
        int kf = ((bx ? ix1 : ix0) * 4 + (by ? iy1 : iy0)) * 4 + (bz ? iz1 : iz0);
        float w = (bx ? tx : 1.f - tx) * (by ? ty : 1.f - ty) * (bz ? tz : 1.f - tz);
        g_ww[(size_t)e * 8 + c] = w * win;
        kp |= (unsigned long long)kf << (8 * c);
    }
    g_kfp[e] = kp;
}

// Build per-(node,bin) entry lists: count -> scan -> fill. One block per node.
__global__ void k_build(const int* __restrict__ dst) {
    __shared__ int cnt[64];
    __shared__ int pos[64];
    int n = blockIdx.x, tid = threadIdx.x;   // 128
    int e0 = g_rowstart[n], e1 = g_rowstart[n + 1];
    if (tid < 64) cnt[tid] = 0;
    __syncthreads();
    for (int e = e0 + tid; e < e1; e += 128) {
        unsigned long long kp = g_kfp[e];
        #pragma unroll
        for (int j = 0; j < 8; j++)
            atomicAdd(&cnt[(int)((kp >> (8 * j)) & 63ull)], 1);
    }
    __syncthreads();
    if (tid == 0) {
        int run = 8 * e0;
        #pragma unroll 1
        for (int k = 0; k < 64; k++) {
            pos[k] = run;
            g_boff[n * 64 + k] = run;
            run += cnt[k];
        }
    }
    __syncthreads();
    for (int e = e0 + tid; e < e1; e += 128) {
        unsigned long long kp = g_kfp[e];
        int d = dst[e];
        const float4* wv = reinterpret_cast<const float4*>(g_ww + (size_t)e * 8);
        float4 wa = wv[0], wb = wv[1];
        float w[8] = {wa.x, wa.y, wa.z, wa.w, wb.x, wb.y, wb.z, wb.w};
        #pragma unroll
        for (int j = 0; j < 8; j++) {
            int k = (int)((kp >> (8 * j)) & 63ull);
            int idx = atomicAdd(&pos[k], 1);
            g_ent[idx] = make_int2(__float_as_int(w[j]), d);
        }
    }
}

// Pad conv0_w (64 bins x 13 cin x 64 cout) -> (64 x 16 x 64), zeros elsewhere.
__global__ void k_padw0(const float* __restrict__ w0) {
    int i = blockIdx.x * blockDim.x + threadIdx.x;
    if (i >= 1024 * 64) return;
    int o  = i & 63;
    int kc = i >> 6;
    int kf = kc >> 4, c = kc & 15;
    g_w0p[i] = (c < 13) ? w0[(kf * 13 + c) * 64 + o] : 0.f;
}

// Pre-convert a layer's W into tf32 hi/lo (done ONCE, not per GEMM block).
__global__ void k_cvtW(const float* __restrict__ W, int total) {
    int i = blockIdx.x * blockDim.x + threadIdx.x;
    if (i >= total) return;
    float x = W[i];
    uint32_t h = f2tf32(x);
    g_Whi[i] = h;
    g_Wlo[i] = f2tf32(x - __uint_as_float(h));
}

// ---------------- feature prep (stride 16, zero-padded) ----------------
__global__ void k_prep0(const float* __restrict__ feats, float* __restrict__ inp) {
    int i = blockIdx.x * blockDim.x + threadIdx.x;
    if (i >= NN * 16) return;
    int n = i >> 4, c = i & 15;
    inp[i] = (c == 0) ? 1.0f : ((c < 13) ? feats[(size_t)n * 12 + (c - 1)] : 0.f);
}

// ---------------- bin-sorted gather: register accumulation, tf32-rounded out -
template<int CIN>
__global__ void k_gather(const float* __restrict__ inp) {
    int n    = blockIdx.x;
    int warp = threadIdx.x >> 5, lane = threadIdx.x & 31;
    const int2* __restrict__ ent = g_ent;
    #pragma unroll 1
    for (int kb = warp * 16; kb < warp * 16 + 16; kb++) {
        int s  = g_boff[n * 64 + kb];
        int se = g_boff[n * 64 + kb + 1];
        if (CIN == 96) {
            float2 a0 = {0.f, 0.f}, a1 = {0.f, 0.f};
            float2 b0 = {0.f, 0.f}, b1 = {0.f, 0.f};
            int i = s;
            for (; i + 1 < se; i += 2) {
                int2 e0 = ent[i], e1 = ent[i + 1];
                float w0 = __int_as_float(e0.x), w1 = __int_as_float(e1.x);
                const float2* f0 = (const float2*)(inp + (size_t)e0.y * 96);
                const float2* f1 = (const float2*)(inp + (size_t)e1.y * 96);
                float2 v0 = f0[lane], v1 = f1[lane];
                a0.x = fmaf(w0, v0.x, a0.x); a0.y = fmaf(w0, v0.y, a0.y);
                b0.x = fmaf(w1, v1.x, b0.x); b0.y = fmaf(w1, v1.y, b0.y);
                if (lane < 16) {
                    float2 u0 = f0[32 + lane], u1 = f1[32 + lane];
                    a1.x = fmaf(w0, u0.x, a1.x); a1.y = fmaf(w0, u0.y, a1.y);
                    b1.x = fmaf(w1, u1.x, b1.x); b1.y = fmaf(w1, u1.y, b1.y);
                }
            }
            if (i < se) {
                int2 e0 = ent[i];
                float w0 = __int_as_float(e0.x);
                const float2* f0 = (const float2*)(inp + (size_t)e0.y * 96);
                float2 v0 = f0[lane];
                a0.x = fmaf(w0, v0.x, a0.x); a0.y = fmaf(w0, v0.y, a0.y);
                if (lane < 16) {
                    float2 u0 = f0[32 + lane];
                    a1.x = fmaf(w0, u0.x, a1.x); a1.y = fmaf(w0, u0.y, a1.y);
                }
            }
            a0.x += b0.x; a0.y += b0.y; a1.x += b1.x; a1.y += b1.y;
            float2* bo = (float2*)(g_B + (size_t)n * 64 * 96 + kb * 96);
            bo[lane] = make_float2(tf32r(a0.x), tf32r(a0.y));
            if (lane < 16) bo[32 + lane] = make_float2(tf32r(a1.x), tf32r(a1.y));
        } else if (CIN == 64) {
            float2 a0 = {0.f, 0.f}, b0 = {0.f, 0.f};
            int i = s;
            for (; i + 1 < se; i += 2) {
                int2 e0 = ent[i], e1 = ent[i + 1];
                float w0 = __int_as_float(e0.x), w1 = __int_as_float(e1.x);
                float2 v0 = ((const float2*)(inp + (size_t)e0.y * 64))[lane];
                float2 v1 = ((const float2*)(inp + (size_t)e1.y * 64))[lane];
                a0.x = fmaf(w0, v0.x, a0.x); a0.y = fmaf(w0, v0.y, a0.y);
                b0.x = fmaf(w1, v1.x, b0.x); b0.y = fmaf(w1, v1.y, b0.y);
            }
            if (i < se) {
                int2 e0 = ent[i];
                float w0 = __int_as_float(e0.x);
                float2 v0 = ((const float2*)(inp + (size_t)e0.y * 64))[lane];
                a0.x = fmaf(w0, v0.x, a0.x); a0.y = fmaf(w0, v0.y, a0.y);
            }
            a0.x += b0.x; a0.y += b0.y;
            ((float2*)(g_B + (size_t)n * 64 * 64 + kb * 64))[lane] =
                make_float2(tf32r(a0.x), tf32r(a0.y));
        } else {  // CIN == 16: quarter-warps process 4 entries concurrently
            int sub = lane >> 3, slot = lane & 7;
            float2 a = {0.f, 0.f};
            for (int i = s + sub; i < se; i += 4) {
                int2 ev = ent[i];
                float w = __int_as_float(ev.x);
                float2 v = ((const float2*)(inp + (size_t)ev.y * 16))[slot];
                a.x = fmaf(w, v.x, a.x); a.y = fmaf(w, v.y, a.y);
            }
            a.x += __shfl_xor_sync(0xffffffffu, a.x, 8);
            a.y += __shfl_xor_sync(0xffffffffu, a.y, 8);
            a.x += __shfl_xor_sync(0xffffffffu, a.x, 16);
            a.y += __shfl_xor_sync(0xffffffffu, a.y, 16);
            if (lane < 8)
                ((float2*)(g_B + (size_t)n * 64 * 16 + kb * 16))[slot] =
                    make_float2(tf32r(a.x), tf32r(a.y));
        }
    }
}

// ---------------- 2-pass TF32 GEMM: C[M,64] = A(tf32)[M,Kd] @ (Whi+Wlo) ------
// A (g_B) is already tf32-rounded by the gather -> no conversion, no Alo.
__global__ void k_gemm_tf32(const float* __restrict__ A,
                            float* __restrict__ C, int M, int Kd) {
    __shared__ uint32_t Ahi[32 * 72];                 // [k][m], stride 72
    __shared__ uint32_t Whi[32 * 72], Wlo[32 * 72];   // [k][n], stride 72
    int tid  = threadIdx.x;          // 128
    int m0   = blockIdx.x * 64;
    int warp = tid >> 5, lane = tid & 31;
    int g = lane >> 2, tq = lane & 3;
    int wm = (warp >> 1) * 32, wn = (warp & 1) * 32;
    float acc[2][4][4];
    #pragma unroll
    for (int mi = 0; mi < 2; mi++)
        #pragma unroll
        for (int ni = 0; ni < 4; ni++)
            #pragma unroll
            for (int q = 0; q < 4; q++) acc[mi][ni][q] = 0.f;

    for (int k0 = 0; k0 < Kd; k0 += 32) {
        #pragma unroll
        for (int i = 0; i < 4; i++) {
            int fi  = tid + 128 * i;
            int row = fi >> 3;
            int kq  = (fi & 7) * 4;
            uint4 v = make_uint4(0u, 0u, 0u, 0u);
            if (m0 + row < M)
                v = *reinterpret_cast<const uint4*>(
                        reinterpret_cast<const uint32_t*>(A) + (size_t)(m0 + row) * Kd + k0 + kq);
            Ahi[(kq + 0) * 72 + row] = v.x;
            Ahi[(kq + 1) * 72 + row] = v.y;
            Ahi[(kq + 2) * 72 + row] = v.z;
            Ahi[(kq + 3) * 72 + row] = v.w;
        }
        #pragma unroll
        for (int i = 0; i < 4; i++) {
            int fi = tid + 128 * i;
            int kk = fi >> 4;
            int nq = (fi & 15) * 4;
            size_t off = (size_t)(k0 + kk) * 64 + nq;
            uint4 hv = *reinterpret_cast<const uint4*>(g_Whi + off);
            uint4 lv = *reinterpret_cast<const uint4*>(g_Wlo + off);
            Whi[kk * 72 + nq + 0] = hv.x; Whi[kk * 72 + nq + 1] = hv.y;
            Whi[kk * 72 + nq + 2] = hv.z; Whi[kk * 72 + nq + 3] = hv.w;
            Wlo[kk * 72 + nq + 0] = lv.x; Wlo[kk * 72 + nq + 1] = lv.y;
            Wlo[kk * 72 + nq + 2] = lv.z; Wlo[kk * 72 + nq + 3] = lv.w;
        }
        __syncthreads();
        #pragma unroll
        for (int ks = 0; ks < 4; ks++) {
            int k8 = ks * 8;
            uint32_t ah[2][4], bh[4][2], bl[4][2];
            #pragma unroll
            for (int mi = 0; mi < 2; mi++) {
                int m = wm + mi * 16 + g;
                ah[mi][0] = Ahi[(k8 + tq) * 72 + m];
                ah[mi][1] = Ahi[(k8 + tq) * 72 + m + 8];
                ah[mi][2] = Ahi[(k8 + tq + 4) * 72 + m];
                ah[mi][3] = Ahi[(k8 + tq + 4) * 72 + m + 8];
            }
            #pragma unroll
            for (int ni = 0; ni < 4; ni++) {
                int n = wn + ni * 8 + g;
                bh[ni][0] = Whi[(k8 + tq) * 72 + n];
                bh[ni][1] = Whi[(k8 + tq + 4) * 72 + n];
                bl[ni][0] = Wlo[(k8 + tq) * 72 + n];
                bl[ni][1] = Wlo[(k8 + tq + 4) * 72 + n];
            }
            #pragma unroll
            for (int mi = 0; mi < 2; mi++)
                #pragma unroll
                for (int ni = 0; ni < 4; ni++) {
                    mma_tf32(acc[mi][ni], ah[mi], bh[ni]);
                    mma_tf32(acc[mi][ni], ah[mi], bl[ni]);
                }
        }
        __syncthreads();
    }
    #pragma unroll
    for (int mi = 0; mi < 2; mi++) {
        int r0 = m0 + wm + mi * 16 + g;
        int r1 = r0 + 8;
        #pragma unroll
        for (int ni = 0; ni < 4; ni++) {
            int c = wn + ni * 8 + 2 * tq;
            if (r0 < M) {
                C[(size_t)r0 * 64 + c]     = acc[mi][ni][0];
                C[(size_t)r0 * 64 + c + 1] = acc[mi][ni][1];
            }
            if (r1 < M) {
                C[(size_t)r1 * 64 + c]     = acc[mi][ni][2];
                C[(size_t)r1 * 64 + c + 1] = acc[mi][ni][3];
            }
        }
    }
}

// ---------------- skinny GEMV (layer 3): y[M,3] = A[M,Kd] @ W3[Kd,3] ---------
__global__ void k_gemv3(const float* __restrict__ A, const float* __restrict__ W3,
                        float* __restrict__ y, int M, int Kd) {
    int gw   = (blockIdx.x * blockDim.x + threadIdx.x) >> 5;
    int lane = threadIdx.x & 31;
    if (gw >= M) return;
    const float* a = A + (size_t)gw * Kd;
    float s0 = 0.f, s1 = 0.f, s2 = 0.f;
    for (int k = lane; k < Kd; k += 32) {
        float av = a[k];
        s0 = fmaf(av, W3[k * 3 + 0], s0);
        s1 = fmaf(av, W3[k * 3 + 1], s1);
        s2 = fmaf(av, W3[k * 3 + 2], s2);
    }
    #pragma unroll
    for (int off = 16; off; off >>= 1) {
        s0 += __shfl_xor_sync(0xffffffffu, s0, off);
        s1 += __shfl_xor_sync(0xffffffffu, s1, off);
        s2 += __shfl_xor_sync(0xffffffffu, s2, off);
    }
    if (lane == 0) {
        y[(size_t)gw * 3 + 0] = s0;
        y[(size_t)gw * 3 + 1] = s1;
        y[(size_t)gw * 3 + 2] = s2;
    }
}

// ---------------- epilogue: conv bias + dense + residual + fused relu --------
__global__ void k_combine(const float* __restrict__ y, const float* __restrict__ cb,
                          const float* __restrict__ dw, const float* __restrict__ db,
                          const float* __restrict__ inp, int cin, int instride,
                          const float* __restrict__ xold, int xold_stride,
                          float* __restrict__ out, float* __restrict__ relu_out,
                          int out_stride, int out_rows,
                          int conv_cols, int dense_cols, int dense_off, float scale) {
    __shared__ float si[96];
    int n = blockIdx.x;
    int o = threadIdx.x;  // 96
    if (o < cin) si[o] = inp[(size_t)n * instride + o];
    __syncthreads();
    int width = dense_off + dense_cols;
    if (conv_cols > width) width = conv_cols;
    if (o >= width || n >= out_rows) return;
    float v = 0.f;
    if (o < conv_cols) v = y[(size_t)n * conv_cols + o] + cb[o];
    if (o >= dense_off) {
        int od = o - dense_off;
        if (od < dense_cols) {
            float s2 = db[od];
            for (int i = 0; i < cin; i++) s2 = fmaf(si[i], dw[i * dense_cols + od], s2);
            v += s2;
        }
    }
    if (xold) v += xold[(size_t)n * xold_stride + o];
    v *= scale;
    out[(size_t)n * out_stride + o] = v;
    if (relu_out) relu_out[(size_t)n * out_stride + o] = fmaxf(v, 0.f);
}

// ---------------- launch ----------------
extern "C" void kernel_launch(void* const* d_in, const int* in_sizes, int n_in,
                              void* d_out, int out_size) {
    const float* pos   = (const float*)d_in[0];
    const float* feats = (const float*)d_in[1];
    const int*   esrc  = (const int*)d_in[2];
    const int*   edst  = (const int*)d_in[3];
    const float* c0w = (const float*)d_in[4];
    const float* c0b = (const float*)d_in[5];
    const float* d0w = (const float*)d_in[6];
    const float* d0b = (const float*)d_in[7];
    const float* c1w = (const float*)d_in[8];
    const float* c1b = (const float*)d_in[9];
    const float* d1w = (const float*)d_in[10];
    const float* d1b = (const float*)d_in[11];
    const float* c2w = (const float*)d_in[12];
    const float* c2b = (const float*)d_in[13];
    const float* d2w = (const float*)d_in[14];
    const float* d2b = (const float*)d_in[15];
    const float* c3w = (const float*)d_in[16];
    const float* c3b = (const float*)d_in[17];
    const float* d3w = (const float*)d_in[18];
    const float* d3b = (const float*)d_in[19];
    float* out = (float*)d_out;

    void *pB, *pA, *pBB, *pI, *pI2, *pY, *pW0;
    cudaGetSymbolAddress(&pB,  g_B);
    cudaGetSymbolAddress(&pA,  g_bufA);
    cudaGetSymbolAddress(&pBB, g_bufB);
    cudaGetSymbolAddress(&pI,  g_inp);
    cudaGetSymbolAddress(&pI2, g_inp2);
    cudaGetSymbolAddress(&pY,  g_y);
    cudaGetSymbolAddress(&pW0, g_w0p);
    float* B    = (float*)pB;
    float* bufA = (float*)pA;
    float* bufB = (float*)pBB;
    float* inp  = (float*)pI;
    float* inp2 = (float*)pI2;
    float* y    = (float*)pY;
    float* w0p  = (float*)pW0;

    const int EB = (EPAD + 255) / 256;
    const int GT = (NN + 63) / 64;   // 313 GEMM M-tiles

    // edge preprocessing (shared across all 4 conv layers)
    k_findpad<<<1, 1>>>(edst);
    k_rowstart<<<(NN + 2 + 255) / 256, 256>>>(esrc);
    k_geom<<<EB, 256>>>(pos, esrc, edst);
    k_build<<<NN, 128>>>(edst);
    k_padw0<<<(1024 * 64 + 255) / 256, 256>>>(c0w);

    // ---- layer 0 (cin 13 padded to 16) ----
    k_prep0<<<(NN * 16 + 255) / 256, 256>>>(feats, inp);
    k_gather<16><<<NN, 128>>>(inp);
    k_cvtW<<<(1024 * 64 + 255) / 256, 256>>>(w0p, 1024 * 64);
    k_gemm_tf32<<<GT, 128>>>(B, y, NN, 64 * 16);
    k_combine<<<NN, 96>>>(y, c0b, d0w, d0b, inp, 13, 16, nullptr, 0,
                          bufA, inp2, 96, NN, 64, 32, 64, 1.f);
    // ---- layer 1 ----
    k_gather<96><<<NN, 128>>>(inp2);
    k_cvtW<<<(6144 * 64 + 255) / 256, 256>>>(c1w, 6144 * 64);
    k_gemm_tf32<<<GT, 128>>>(B, y, NN, 64 * 96);
    k_combine<<<NN, 96>>>(y, c1b, d1w, d1b, inp2, 96, 96, nullptr, 0,
                          bufB, inp, 64, NN, 64, 64, 0, 1.f);
    // ---- layer 2 (residual) ----
    k_gather<64><<<NN, 128>>>(inp);
    k_cvtW<<<(4096 * 64 + 255) / 256, 256>>>(c2w, 4096 * 64);
    k_gemm_tf32<<<GT, 128>>>(B, y, NN, 64 * 64);
    k_combine<<<NN, 96>>>(y, c2b, d2w, d2b, inp, 64, 64, bufB, 64,
                          bufA, inp2, 64, NN, 64, 64, 0, 1.f);
    // ---- layer 3 (output, /128, first 20000 rows) ----
    k_gather<64><<<NN, 128>>>(inp2);
    k_gemv3<<<(NN * 32 + 255) / 256, 256>>>(B, c3w, y, NN, 64 * 64);
    k_combine<<<NREAL, 96>>>(y, c3b, d3w, d3b, inp2, 64, 64, nullptr, 0,
                             out, nullptr, 3, NREAL, 3, 3, 0, 1.f / 128.f);
}

// round 14
// speedup vs baseline: 1.4302x; 1.4302x over previous
#include <cuda_runtime.h>
#include <math.h>
#include <stdint.h>

#define NN     20001
#define NREAL  20000
#define EPAD   1200000
#define RADIUS_F 0.1125f

// ---------------- scratch (device globals; no allocations) ----------------
__device__ float g_B[(size_t)NN * 64 * 96];        // bin accumulator (tf32-rounded), max cin=96
__device__ float g_bufA[(size_t)NN * 96];
__device__ float g_bufB[(size_t)NN * 96];
__device__ float g_inp[(size_t)NN * 96];
__device__ float g_inp2[(size_t)NN * 96];
__device__ float g_y[(size_t)NN * 64];
__device__ float g_ww[(size_t)EPAD * 8];           // win * trilinear weight per corner
__device__ unsigned long long g_kfp[EPAD];         // 8 packed 6-bit kernel indices
__device__ int2 g_ent[(size_t)EPAD * 8];           // (weight bits, dst) sorted by (node,bin)
__device__ int g_boff[NN * 64 + 1];                // per-(node,bin) entry offsets
__device__ float g_w0p[1024 * 64];                 // conv0_w padded cin 13->16
__device__ uint32_t g_Whi[6144 * 64];              // tf32 hi of current layer W
__device__ uint32_t g_Wlo[6144 * 64];              // tf32 lo of current layer W
__device__ int g_rowstart[NN + 2];
__device__ int g_Ereal;

// ---------------- helpers ----------------
__device__ __forceinline__ float fsign(float v) {
    return (v > 0.f) ? 1.f : ((v < 0.f) ? -1.f : 0.f);
}

__device__ __forceinline__ uint32_t f2tf32(float x) {
    uint32_t r;
    asm("cvt.rna.tf32.f32 %0, %1;" : "=r"(r) : "f"(x));
    return r;
}

__device__ __forceinline__ float tf32r(float x) {
    return __uint_as_float(f2tf32(x));
}

__device__ __forceinline__ void mma_tf32(float* d, const uint32_t* a, const uint32_t* b) {
    asm volatile(
        "mma.sync.aligned.m16n8k8.row.col.f32.tf32.tf32.f32 "
        "{%0,%1,%2,%3}, {%4,%5,%6,%7}, {%8,%9}, {%0,%1,%2,%3};"
        : "+f"(d[0]), "+f"(d[1]), "+f"(d[2]), "+f"(d[3])
        : "r"(a[0]), "r"(a[1]), "r"(a[2]), "r"(a[3]), "r"(b[0]), "r"(b[1]));
}

__device__ __forceinline__ void ball_to_cube(float x, float y, float z,
                                             float& a, float& b, float& zc) {
    const float eps = 1e-9f;
    float sq   = x * x + y * y + z * z;
    float norm = sqrtf(sq + eps);
    float rxy2 = x * x + y * y;
    bool  polar = 1.25f * z * z > rxy2;
    float s = polar ? sqrtf(3.f * norm / (norm + fabsf(z) + eps))
                    : norm / sqrtf(rxy2 + eps);
    float xc = x * s;
    float yc = y * s;
    float zz = polar ? fsign(z) * norm : 1.5f * z;
    if (sq < 1e-12f) { xc = 0.f; yc = 0.f; zz = 0.f; }
    float r  = sqrtf(xc * xc + yc * yc + eps);
    bool  c1 = fabsf(xc) >= fabsf(yc);
    float xs = (fabsf(xc) < eps) ? eps : xc;
    float ys = (fabsf(yc) < eps) ? eps : yc;
    const float fop = 1.27323954473516268615f;  // 4/pi
    float av = c1 ? fsign(xc) * r : fsign(yc) * r * fop * atanf(xc / ys);
    float bv = c1 ? fsign(xc) * r * fop * atanf(yc / xs) : fsign(yc) * r;
    if (xc * xc + yc * yc < 1e-12f) { av = 0.f; bv = 0.f; }
    a = av; b = bv; zc = zz;
}

// ---------------- setup kernels ----------------
__global__ void k_findpad(const int* __restrict__ dst) {
    int lo = 0, hi = EPAD;
    while (lo < hi) {
        int mid = (lo + hi) >> 1;
        if (dst[mid] < NREAL) lo = mid + 1; else hi = mid;
    }
    g_Ereal = lo;
    g_boff[NN * 64] = 8 * lo;   // sentinel
}

__global__ void k_rowstart(const int* __restrict__ src) {
    int i = blockIdx.x * blockDim.x + threadIdx.x;
    if (i > NN) return;
    int E = g_Ereal;
    int lo = 0, hi = E;
    while (lo < hi) {
        int mid = (lo + hi) >> 1;
        if (src[mid] < i) lo = mid + 1; else hi = mid;
    }
    g_rowstart[i] = lo;
}

__global__ void k_geom(const float* __restrict__ pos,
                       const int* __restrict__ src,
                       const int* __restrict__ dst) {
    int e = blockIdx.x * blockDim.x + threadIdx.x;
    if (e >= EPAD) return;
    int d = dst[e];
    if (d >= NREAL) return;  // pad edge (win == 0)
    int s = src[e];
    float ox = (pos[(size_t)d * 3 + 0] - pos[(size_t)s * 3 + 0]) * (1.f / RADIUS_F);
    float oy = (pos[(size_t)d * 3 + 1] - pos[(size_t)s * 3 + 1]) * (1.f / RADIUS_F);
    float oz = (pos[(size_t)d * 3 + 2] - pos[(size_t)s * 3 + 2]) * (1.f / RADIUS_F);
    float r2 = ox * ox + oy * oy + oz * oz;
    float u  = 1.f - r2;
    float win = u * u * u;
    win = fminf(fmaxf(win, 0.f), 1.f);
    float ca, cb, cc;
    ball_to_cube(ox, oy, oz, ca, cb, cc);
    float gx = fminf(fmaxf((ca * 0.5f + 0.5f) * 3.f, 0.f), 3.f);
    float gy = fminf(fmaxf((cb * 0.5f + 0.5f) * 3.f, 0.f), 3.f);
    float gz = fminf(fmaxf((cc * 0.5f + 0.5f) * 3.f, 0.f), 3.f);
    float fx = floorf(gx), fy = floorf(gy), fz = floorf(gz);
    float tx = gx - fx, ty = gy - fy, tz = gz - fz;
    int ix0 = min((int)fx, 3), ix1 = min((int)fx + 1, 3);
    int iy0 = min((int)fy, 3), iy1 = min((int)fy + 1, 3);
    int iz0 = min((int)fz, 3), iz1 = min((int)fz + 1, 3);
    unsigned long long kp = 0;
    #pragma unroll
    for (int c = 0; c < 8; c++) {
        int bx = (c >> 2) & 1, by = (c >> 1) & 1, bz = c & 1;
        int kf = ((bx ? ix1 : ix0) * 4 + (by ? iy1 : iy0)) * 4 + (bz ? iz1 : iz0);
        float w = (bx ? tx : 1.f - tx) * (by ? ty : 1.f - ty) * (bz ? tz : 1.f - tz);
        g_ww[(size_t)e * 8 + c] = w * win;
        kp |= (unsigned long long)kf << (8 * c);
    }
    g_kfp[e] = kp;
}

// Build per-(node,bin) entry lists: count -> scan -> fill. One block per node.
__global__ void k_build(const int* __restrict__ dst) {
    __shared__ int cnt[64];
    __shared__ int pos[64];
    int n = blockIdx.x, tid = threadIdx.x;   // 128
    int e0 = g_rowstart[n], e1 = g_rowstart[n + 1];
    if (tid < 64) cnt[tid] = 0;
    __syncthreads();
    for (int e = e0 + tid; e < e1; e += 128) {
        unsigned long long kp = g_kfp[e];
        #pragma unroll
        for (int j = 0; j < 8; j++)
            atomicAdd(&cnt[(int)((kp >> (8 * j)) & 63ull)], 1);
    }
    __syncthreads();
    if (tid == 0) {
        int run = 8 * e0;
        #pragma unroll 1
        for (int k = 0; k < 64; k++) {
            pos[k] = run;
            g_boff[n * 64 + k] = run;
            run += cnt[k];
        }
    }
    __syncthreads();
    for (int e = e0 + tid; e < e1; e += 128) {
        unsigned long long kp = g_kfp[e];
        int d = dst[e];
        const float4* wv = reinterpret_cast<const float4*>(g_ww + (size_t)e * 8);
        float4 wa = wv[0], wb = wv[1];
        float w[8] = {wa.x, wa.y, wa.z, wa.w, wb.x, wb.y, wb.z, wb.w};
        #pragma unroll
        for (int j = 0; j < 8; j++) {
            int k = (int)((kp >> (8 * j)) & 63ull);
            int idx = atomicAdd(&pos[k], 1);
            g_ent[idx] = make_int2(__float_as_int(w[j]), d);
        }
    }
}

// Pad conv0_w (64 bins x 13 cin x 64 cout) -> (64 x 16 x 64), zeros elsewhere.
__global__ void k_padw0(const float* __restrict__ w0) {
    int i = blockIdx.x * blockDim.x + threadIdx.x;
    if (i >= 1024 * 64) return;
    int o  = i & 63;
    int kc = i >> 6;
    int kf = kc >> 4, c = kc & 15;
    g_w0p[i] = (c < 13) ? w0[(kf * 13 + c) * 64 + o] : 0.f;
}

// Pre-convert a layer's W into tf32 hi/lo (done ONCE, not per GEMM block).
__global__ void k_cvtW(const float* __restrict__ W, int total4) {
    int i = blockIdx.x * blockDim.x + threadIdx.x;
    if (i >= total4) return;
    float4 x = reinterpret_cast<const float4*>(W)[i];
    uint4 h, l;
    h.x = f2tf32(x.x); l.x = f2tf32(x.x - __uint_as_float(h.x));
    h.y = f2tf32(x.y); l.y = f2tf32(x.y - __uint_as_float(h.y));
    h.z = f2tf32(x.z); l.z = f2tf32(x.z - __uint_as_float(h.z));
    h.w = f2tf32(x.w); l.w = f2tf32(x.w - __uint_as_float(h.w));
    reinterpret_cast<uint4*>(g_Whi)[i] = h;
    reinterpret_cast<uint4*>(g_Wlo)[i] = l;
}

// ---------------- feature prep (stride 16, zero-padded) ----------------
__global__ void k_prep0(const float* __restrict__ feats, float* __restrict__ inp) {
    int i = blockIdx.x * blockDim.x + threadIdx.x;
    if (i >= NN * 16) return;
    int n = i >> 4, c = i & 15;
    inp[i] = (c == 0) ? 1.0f : ((c < 13) ? feats[(size_t)n * 12 + (c - 1)] : 0.f);
}

// ---------------- bin-sorted gather: register accumulation, tf32-rounded out -
template<int CIN>
__global__ void k_gather(const float* __restrict__ inp) {
    int n    = blockIdx.x;
    int warp = threadIdx.x >> 5, lane = threadIdx.x & 31;
    const int2* __restrict__ ent = g_ent;
    #pragma unroll 1
    for (int kb = warp * 16; kb < warp * 16 + 16; kb++) {
        int s  = g_boff[n * 64 + kb];
        int se = g_boff[n * 64 + kb + 1];
        if (CIN == 96) {
            float2 a0 = {0.f, 0.f}, a1 = {0.f, 0.f};
            float2 b0 = {0.f, 0.f}, b1 = {0.f, 0.f};
            int i = s;
            for (; i + 1 < se; i += 2) {
                int2 e0 = ent[i], e1 = ent[i + 1];
                float w0 = __int_as_float(e0.x), w1 = __int_as_float(e1.x);
                const float2* f0 = (const float2*)(inp + (size_t)e0.y * 96);
                const float2* f1 = (const float2*)(inp + (size_t)e1.y * 96);
                float2 v0 = f0[lane], v1 = f1[lane];
                a0.x = fmaf(w0, v0.x, a0.x); a0.y = fmaf(w0, v0.y, a0.y);
                b0.x = fmaf(w1, v1.x, b0.x); b0.y = fmaf(w1, v1.y, b0.y);
                if (lane < 16) {
                    float2 u0 = f0[32 + lane], u1 = f1[32 + lane];
                    a1.x = fmaf(w0, u0.x, a1.x); a1.y = fmaf(w0, u0.y, a1.y);
                    b1.x = fmaf(w1, u1.x, b1.x); b1.y = fmaf(w1, u1.y, b1.y);
                }
            }
            if (i < se) {
                int2 e0 = ent[i];
                float w0 = __int_as_float(e0.x);
                const float2* f0 = (const float2*)(inp + (size_t)e0.y * 96);
                float2 v0 = f0[lane];
                a0.x = fmaf(w0, v0.x, a0.x); a0.y = fmaf(w0, v0.y, a0.y);
                if (lane < 16) {
                    float2 u0 = f0[32 + lane];
                    a1.x = fmaf(w0, u0.x, a1.x); a1.y = fmaf(w0, u0.y, a1.y);
                }
            }
            a0.x += b0.x; a0.y += b0.y; a1.x += b1.x; a1.y += b1.y;
            float2* bo = (float2*)(g_B + (size_t)n * 64 * 96 + kb * 96);
            bo[lane] = make_float2(tf32r(a0.x), tf32r(a0.y));
            if (lane < 16) bo[32 + lane] = make_float2(tf32r(a1.x), tf32r(a1.y));
        } else if (CIN == 64) {
            float2 a0 = {0.f, 0.f}, b0 = {0.f, 0.f};
            int i = s;
            for (; i + 1 < se; i += 2) {
                int2 e0 = ent[i], e1 = ent[i + 1];
                float w0 = __int_as_float(e0.x), w1 = __int_as_float(e1.x);
                float2 v0 = ((const float2*)(inp + (size_t)e0.y * 64))[lane];
                float2 v1 = ((const float2*)(inp + (size_t)e1.y * 64))[lane];
                a0.x = fmaf(w0, v0.x, a0.x); a0.y = fmaf(w0, v0.y, a0.y);
                b0.x = fmaf(w1, v1.x, b0.x); b0.y = fmaf(w1, v1.y, b0.y);
            }
            if (i < se) {
                int2 e0 = ent[i];
                float w0 = __int_as_float(e0.x);
                float2 v0 = ((const float2*)(inp + (size_t)e0.y * 64))[lane];
                a0.x = fmaf(w0, v0.x, a0.x); a0.y = fmaf(w0, v0.y, a0.y);
            }
            a0.x += b0.x; a0.y += b0.y;
            ((float2*)(g_B + (size_t)n * 64 * 64 + kb * 64))[lane] =
                make_float2(tf32r(a0.x), tf32r(a0.y));
        } else {  // CIN == 16: quarter-warps process 4 entries concurrently
            int sub = lane >> 3, slot = lane & 7;
            float2 a = {0.f, 0.f};
            for (int i = s + sub; i < se; i += 4) {
                int2 ev = ent[i];
                float w = __int_as_float(ev.x);
                float2 v = ((const float2*)(inp + (size_t)ev.y * 16))[slot];
                a.x = fmaf(w, v.x, a.x); a.y = fmaf(w, v.y, a.y);
            }
            a.x += __shfl_xor_sync(0xffffffffu, a.x, 8);
            a.y += __shfl_xor_sync(0xffffffffu, a.y, 8);
            a.x += __shfl_xor_sync(0xffffffffu, a.x, 16);
            a.y += __shfl_xor_sync(0xffffffffu, a.y, 16);
            if (lane < 8)
                ((float2*)(g_B + (size_t)n * 64 * 16 + kb * 16))[slot] =
                    make_float2(tf32r(a.x), tf32r(a.y));
        }
    }
}

// ---------------- 2-pass TF32 GEMM: C[M,64] = A(tf32)[M,Kd] @ (Whi+Wlo) ------
// A (g_B) is already tf32-rounded by the gather -> no conversion, no Alo.
__global__ void k_gemm_tf32(const float* __restrict__ A,
                            float* __restrict__ C, int M, int Kd) {
    __shared__ uint32_t Ahi[32 * 72];                 // [k][m], stride 72
    __shared__ uint32_t Whi[32 * 72], Wlo[32 * 72];   // [k][n], stride 72
    int tid  = threadIdx.x;          // 128
    int m0   = blockIdx.x * 64;
    int warp = tid >> 5, lane = tid & 31;
    int g = lane >> 2, tq = lane & 3;
    int wm = (warp >> 1) * 32, wn = (warp & 1) * 32;
    float acc[2][4][4];
    #pragma unroll
    for (int mi = 0; mi < 2; mi++)
        #pragma unroll
        for (int ni = 0; ni < 4; ni++)
            #pragma unroll
            for (int q = 0; q < 4; q++) acc[mi][ni][q] = 0.f;

    for (int k0 = 0; k0 < Kd; k0 += 32) {
        #pragma unroll
        for (int i = 0; i < 4; i++) {
            int fi  = tid + 128 * i;
            int row = fi >> 3;
            int kq  = (fi & 7) * 4;
            uint4 v = make_uint4(0u, 0u, 0u, 0u);
            if (m0 + row < M)
                v = *reinterpret_cast<const uint4*>(
                        reinterpret_cast<const uint32_t*>(A) + (size_t)(m0 + row) * Kd + k0 + kq);
            Ahi[(kq + 0) * 72 + row] = v.x;
            Ahi[(kq + 1) * 72 + row] = v.y;
            Ahi[(kq + 2) * 72 + row] = v.z;
            Ahi[(kq + 3) * 72 + row] = v.w;
        }
        #pragma unroll
        for (int i = 0; i < 4; i++) {
            int fi = tid + 128 * i;
            int kk = fi >> 4;
            int nq = (fi & 15) * 4;
            size_t off = (size_t)(k0 + kk) * 64 + nq;
            uint4 hv = *reinterpret_cast<const uint4*>(g_Whi + off);
            uint4 lv = *reinterpret_cast<const uint4*>(g_Wlo + off);
            Whi[kk * 72 + nq + 0] = hv.x; Whi[kk * 72 + nq + 1] = hv.y;
            Whi[kk * 72 + nq + 2] = hv.z; Whi[kk * 72 + nq + 3] = hv.w;
            Wlo[kk * 72 + nq + 0] = lv.x; Wlo[kk * 72 + nq + 1] = lv.y;
            Wlo[kk * 72 + nq + 2] = lv.z; Wlo[kk * 72 + nq + 3] = lv.w;
        }
        __syncthreads();
        #pragma unroll
        for (int ks = 0; ks < 4; ks++) {
            int k8 = ks * 8;
            uint32_t ah[2][4], bh[4][2], bl[4][2];
            #pragma unroll
            for (int mi = 0; mi < 2; mi++) {
                int m = wm + mi * 16 + g;
                ah[mi][0] = Ahi[(k8 + tq) * 72 + m];
                ah[mi][1] = Ahi[(k8 + tq) * 72 + m + 8];
                ah[mi][2] = Ahi[(k8 + tq + 4) * 72 + m];
                ah[mi][3] = Ahi[(k8 + tq + 4) * 72 + m + 8];
            }
            #pragma unroll
            for (int ni = 0; ni < 4; ni++) {
                int n = wn + ni * 8 + g;
                bh[ni][0] = Whi[(k8 + tq) * 72 + n];
                bh[ni][1] = Whi[(k8 + tq + 4) * 72 + n];
                bl[ni][0] = Wlo[(k8 + tq) * 72 + n];
                bl[ni][1] = Wlo[(k8 + tq + 4) * 72 + n];
            }
            #pragma unroll
            for (int mi = 0; mi < 2; mi++)
                #pragma unroll
                for (int ni = 0; ni < 4; ni++) {
                    mma_tf32(acc[mi][ni], ah[mi], bh[ni]);
                    mma_tf32(acc[mi][ni], ah[mi], bl[ni]);
                }
        }
        __syncthreads();
    }
    #pragma unroll
    for (int mi = 0; mi < 2; mi++) {
        int r0 = m0 + wm + mi * 16 + g;
        int r1 = r0 + 8;
        #pragma unroll
        for (int ni = 0; ni < 4; ni++) {
            int c = wn + ni * 8 + 2 * tq;
            if (r0 < M) {
                C[(size_t)r0 * 64 + c]     = acc[mi][ni][0];
                C[(size_t)r0 * 64 + c + 1] = acc[mi][ni][1];
            }
            if (r1 < M) {
                C[(size_t)r1 * 64 + c]     = acc[mi][ni][2];
                C[(size_t)r1 * 64 + c + 1] = acc[mi][ni][3];
            }
        }
    }
}

// ---------------- skinny GEMV (layer 3): y[M,3] = A[M,Kd] @ W3[Kd,3] ---------
__global__ void k_gemv3(const float* __restrict__ A, const float* __restrict__ W3,
                        float* __restrict__ y, int M, int Kd) {
    int gw   = (blockIdx.x * blockDim.x + threadIdx.x) >> 5;
    int lane = threadIdx.x & 31;
    if (gw >= M) return;
    const float4* a4 = (const float4*)(A + (size_t)gw * Kd);
    float s0 = 0.f, s1 = 0.f, s2 = 0.f;
    for (int k4 = lane; k4 < Kd / 4; k4 += 32) {
        float4 av = a4[k4];
        int k = k4 * 4;
        s0 = fmaf(av.x, W3[k * 3 + 0], s0);
        s1 = fmaf(av.x, W3[k * 3 + 1], s1);
        s2 = fmaf(av.x, W3[k * 3 + 2], s2);
        s0 = fmaf(av.y, W3[k * 3 + 3], s0);
        s1 = fmaf(av.y, W3[k * 3 + 4], s1);
        s2 = fmaf(av.y, W3[k * 3 + 5], s2);
        s0 = fmaf(av.z, W3[k * 3 + 6], s0);
        s1 = fmaf(av.z, W3[k * 3 + 7], s1);
        s2 = fmaf(av.z, W3[k * 3 + 8], s2);
        s0 = fmaf(av.w, W3[k * 3 + 9], s0);
        s1 = fmaf(av.w, W3[k * 3 + 10], s1);
        s2 = fmaf(av.w, W3[k * 3 + 11], s2);
    }
    #pragma unroll
    for (int off = 16; off; off >>= 1) {
        s0 += __shfl_xor_sync(0xffffffffu, s0, off);
        s1 += __shfl_xor_sync(0xffffffffu, s1, off);
        s2 += __shfl_xor_sync(0xffffffffu, s2, off);
    }
    if (lane == 0) {
        y[(size_t)gw * 3 + 0] = s0;
        y[(size_t)gw * 3 + 1] = s1;
        y[(size_t)gw * 3 + 2] = s2;
    }
}

// ---------------- epilogue: conv bias + dense + residual + fused relu --------
__global__ void k_combine(const float* __restrict__ y, const float* __restrict__ cb,
                          const float* __restrict__ dw, const float* __restrict__ db,
                          const float* __restrict__ inp, int cin, int instride,
                          const float* __restrict__ xold, int xold_stride,
                          float* __restrict__ out, float* __restrict__ relu_out,
                          int out_stride, int out_rows,
                          int conv_cols, int dense_cols, int dense_off, float scale) {
    __shared__ float si[96];
    int n = blockIdx.x;
    int o = threadIdx.x;  // 96
    if (o < cin) si[o] = inp[(size_t)n * instride + o];
    __syncthreads();
    int width = dense_off + dense_cols;
    if (conv_cols > width) width = conv_cols;
    if (o >= width || n >= out_rows) return;
    float v = 0.f;
    if (o < conv_cols) v = y[(size_t)n * conv_cols + o] + cb[o];
    if (o >= dense_off) {
        int od = o - dense_off;
        if (od < dense_cols) {
            float s2 = db[od];
            for (int i = 0; i < cin; i++) s2 = fmaf(si[i], dw[i * dense_cols + od], s2);
            v += s2;
        }
    }
    if (xold) v += xold[(size_t)n * xold_stride + o];
    v *= scale;
    out[(size_t)n * out_stride + o] = v;
    if (relu_out) relu_out[(size_t)n * out_stride + o] = fmaxf(v, 0.f);
}

// ---------------- launch ----------------
extern "C" void kernel_launch(void* const* d_in, const int* in_sizes, int n_in,
                              void* d_out, int out_size) {
    const float* pos   = (const float*)d_in[0];
    const float* feats = (const float*)d_in[1];
    const int*   esrc  = (const int*)d_in[2];
    const int*   edst  = (const int*)d_in[3];
    const float* c0w = (const float*)d_in[4];
    const float* c0b = (const float*)d_in[5];
    const float* d0w = (const float*)d_in[6];
    const float* d0b = (const float*)d_in[7];
    const float* c1w = (const float*)d_in[8];
    const float* c1b = (const float*)d_in[9];
    const float* d1w = (const float*)d_in[10];
    const float* d1b = (const float*)d_in[11];
    const float* c2w = (const float*)d_in[12];
    const float* c2b = (const float*)d_in[13];
    const float* d2w = (const float*)d_in[14];
    const float* d2b = (const float*)d_in[15];
    const float* c3w = (const float*)d_in[16];
    const float* c3b = (const float*)d_in[17];
    const float* d3w = (const float*)d_in[18];
    const float* d3b = (const float*)d_in[19];
    float* out = (float*)d_out;

    void *pB, *pA, *pBB, *pI, *pI2, *pY, *pW0;
    cudaGetSymbolAddress(&pB,  g_B);
    cudaGetSymbolAddress(&pA,  g_bufA);
    cudaGetSymbolAddress(&pBB, g_bufB);
    cudaGetSymbolAddress(&pI,  g_inp);
    cudaGetSymbolAddress(&pI2, g_inp2);
    cudaGetSymbolAddress(&pY,  g_y);
    cudaGetSymbolAddress(&pW0, g_w0p);
    float* B    = (float*)pB;
    float* bufA = (float*)pA;
    float* bufB = (float*)pBB;
    float* inp  = (float*)pI;
    float* inp2 = (float*)pI2;
    float* y    = (float*)pY;
    float* w0p  = (float*)pW0;

    const int EB = (EPAD + 255) / 256;
    const int GT = (NN + 63) / 64;   // 313 GEMM M-tiles

    // edge preprocessing (shared across all 4 conv layers)
    k_findpad<<<1, 1>>>(edst);
    k_rowstart<<<(NN + 2 + 255) / 256, 256>>>(esrc);
    k_geom<<<EB, 256>>>(pos, esrc, edst);
    k_build<<<NN, 128>>>(edst);
    k_padw0<<<(1024 * 64 + 255) / 256, 256>>>(c0w);

    // ---- layer 0 (cin 13 padded to 16) ----
    k_prep0<<<(NN * 16 + 255) / 256, 256>>>(feats, inp);
    k_gather<16><<<NN, 128>>>(inp);
    k_cvtW<<<(1024 * 16 + 255) / 256, 256>>>(w0p, 1024 * 16);
    k_gemm_tf32<<<GT, 128>>>(B, y, NN, 64 * 16);
    k_combine<<<NN, 96>>>(y, c0b, d0w, d0b, inp, 13, 16, nullptr, 0,
                          bufA, inp2, 96, NN, 64, 32, 64, 1.f);
    // ---- layer 1 ----
    k_gather<96><<<NN, 128>>>(inp2);
    k_cvtW<<<(6144 * 16 + 255) / 256, 256>>>(c1w, 6144 * 16);
    k_gemm_tf32<<<GT, 128>>>(B, y, NN, 64 * 96);
    k_combine<<<NN, 96>>>(y, c1b, d1w, d1b, inp2, 96, 96, nullptr, 0,
                          bufB, inp, 64, NN, 64, 64, 0, 1.f);
    // ---- layer 2 (residual) ----
    k_gather<64><<<NN, 128>>>(inp);
    k_cvtW<<<(4096 * 16 + 255) / 256, 256>>>(c2w, 4096 * 16);
    k_gemm_tf32<<<GT, 128>>>(B, y, NN, 64 * 64);
    k_combine<<<NN, 96>>>(y, c2b, d2w, d2b, inp, 64, 64, bufB, 64,
                          bufA, inp2, 64, NN, 64, 64, 0, 1.f);
    // ---- layer 3 (output, /128, first 20000 rows) ----
    k_gather<64><<<NN, 128>>>(inp2);
    k_gemv3<<<(NN * 32 + 255) / 256, 256>>>(B, c3w, y, NN, 64 * 64);
    k_combine<<<NREAL, 96>>>(y, c3b, d3w, d3b, inp2, 64, 64, nullptr, 0,
                             out, nullptr, 3, NREAL, 3, 3, 0, 1.f / 128.f);
}

// round 16
// speedup vs baseline: 1.4959x; 1.0459x over previous
#include <cuda_runtime.h>
#include <math.h>
#include <stdint.h>

#define NN     20001
#define NREAL  20000
#define EPAD   1200000
#define RADIUS_F 0.1125f

// ---------------- scratch (device globals; no allocations) ----------------
__device__ float g_B[(size_t)NN * 64 * 96];        // bin accumulator (tf32-rounded), max cin=96
__device__ float g_bufA[(size_t)NN * 96];
__device__ float g_bufB[(size_t)NN * 96];
__device__ float g_inp[(size_t)NN * 96];
__device__ float g_inp2[(size_t)NN * 96];
__device__ float g_y[(size_t)NN * 64];
__device__ float g_ww[(size_t)EPAD * 8];           // win * trilinear weight per corner
__device__ unsigned long long g_kfp[EPAD];         // 8 packed 6-bit kernel indices
__device__ int2 g_ent[(size_t)EPAD * 8];           // (weight bits, dst) sorted by (node,bin)
__device__ int g_boff[NN * 64 + 1];                // per-(node,bin) entry offsets
__device__ float g_w0p[1024 * 64];                 // conv0_w padded cin 13->16
__device__ uint32_t g_Whi[6144 * 64];              // tf32-rounded current layer W (bits)
__device__ int g_rowstart[NN + 2];
__device__ int g_Ereal;

// ---------------- helpers ----------------
__device__ __forceinline__ float fsign(float v) {
    return (v > 0.f) ? 1.f : ((v < 0.f) ? -1.f : 0.f);
}

__device__ __forceinline__ uint32_t f2tf32(float x) {
    uint32_t r;
    asm("cvt.rna.tf32.f32 %0, %1;" : "=r"(r) : "f"(x));
    return r;
}

__device__ __forceinline__ float tf32r(float x) {
    return __uint_as_float(f2tf32(x));
}

__device__ __forceinline__ void mma_tf32(float* d, const uint32_t* a, const uint32_t* b) {
    asm volatile(
        "mma.sync.aligned.m16n8k8.row.col.f32.tf32.tf32.f32 "
        "{%0,%1,%2,%3}, {%4,%5,%6,%7}, {%8,%9}, {%0,%1,%2,%3};"
        : "+f"(d[0]), "+f"(d[1]), "+f"(d[2]), "+f"(d[3])
        : "r"(a[0]), "r"(a[1]), "r"(a[2]), "r"(a[3]), "r"(b[0]), "r"(b[1]));
}

__device__ __forceinline__ void ball_to_cube(float x, float y, float z,
                                             float& a, float& b, float& zc) {
    const float eps = 1e-9f;
    float sq   = x * x + y * y + z * z;
    float norm = sqrtf(sq + eps);
    float rxy2 = x * x + y * y;
    bool  polar = 1.25f * z * z > rxy2;
    float s = polar ? sqrtf(3.f * norm / (norm + fabsf(z) + eps))
                    : norm / sqrtf(rxy2 + eps);
    float xc = x * s;
    float yc = y * s;
    float zz = polar ? fsign(z) * norm : 1.5f * z;
    if (sq < 1e-12f) { xc = 0.f; yc = 0.f; zz = 0.f; }
    float r  = sqrtf(xc * xc + yc * yc + eps);
    bool  c1 = fabsf(xc) >= fabsf(yc);
    float xs = (fabsf(xc) < eps) ? eps : xc;
    float ys = (fabsf(yc) < eps) ? eps : yc;
    const float fop = 1.27323954473516268615f;  // 4/pi
    float av = c1 ? fsign(xc) * r : fsign(yc) * r * fop * atanf(xc / ys);
    float bv = c1 ? fsign(xc) * r * fop * atanf(yc / xs) : fsign(yc) * r;
    if (xc * xc + yc * yc < 1e-12f) { av = 0.f; bv = 0.f; }
    a = av; b = bv; zc = zz;
}

// ---------------- setup kernels ----------------
__global__ void k_findpad(const int* __restrict__ dst) {
    int lo = 0, hi = EPAD;
    while (lo < hi) {
        int mid = (lo + hi) >> 1;
        if (dst[mid] < NREAL) lo = mid + 1; else hi = mid;
    }
    g_Ereal = lo;
    g_boff[NN * 64] = 8 * lo;   // sentinel
}

__global__ void k_rowstart(const int* __restrict__ src) {
    int i = blockIdx.x * blockDim.x + threadIdx.x;
    if (i > NN) return;
    int E = g_Ereal;
    int lo = 0, hi = E;
    while (lo < hi) {
        int mid = (lo + hi) >> 1;
        if (src[mid] < i) lo = mid + 1; else hi = mid;
    }
    g_rowstart[i] = lo;
}

__global__ void k_geom(const float* __restrict__ pos,
                       const int* __restrict__ src,
                       const int* __restrict__ dst) {
    int e = blockIdx.x * blockDim.x + threadIdx.x;
    if (e >= EPAD) return;
    int d = dst[e];
    if (d >= NREAL) return;  // pad edge (win == 0)
    int s = src[e];
    float ox = (pos[(size_t)d * 3 + 0] - pos[(size_t)s * 3 + 0]) * (1.f / RADIUS_F);
    float oy = (pos[(size_t)d * 3 + 1] - pos[(size_t)s * 3 + 1]) * (1.f / RADIUS_F);
    float oz = (pos[(size_t)d * 3 + 2] - pos[(size_t)s * 3 + 2]) * (1.f / RADIUS_F);
    float r2 = ox * ox + oy * oy + oz * oz;
    float u  = 1.f - r2;
    float win = u * u * u;
    win = fminf(fmaxf(win, 0.f), 1.f);
    float ca, cb, cc;
    ball_to_cube(ox, oy, oz, ca, cb, cc);
    float gx = fminf(fmaxf((ca * 0.5f + 0.5f) * 3.f, 0.f), 3.f);
    float gy = fminf(fmaxf((cb * 0.5f + 0.5f) * 3.f, 0.f), 3.f);
    float gz = fminf(fmaxf((cc * 0.5f + 0.5f) * 3.f, 0.f), 3.f);
    float fx = floorf(gx), fy = floorf(gy), fz = floorf(gz);
    float tx = gx - fx, ty = gy - fy, tz = gz - fz;
    int ix0 = min((int)fx, 3), ix1 = min((int)fx + 1, 3);
    int iy0 = min((int)fy, 3), iy1 = min((int)fy + 1, 3);
    int iz0 = min((int)fz, 3), iz1 = min((int)fz + 1, 3);
    unsigned long long kp = 0;
    #pragma unroll
    for (int c = 0; c < 8; c++) {
        int bx = (c >> 2) & 1, by = (c >> 1) & 1, bz = c & 1;
        int kf = ((bx ? ix1 : ix0) * 4 + (by ? iy1 : iy0)) * 4 + (bz ? iz1 : iz0);
        float w = (bx ? tx : 1.f - tx) * (by ? ty : 1.f - ty) * (bz ? tz : 1.f - tz);
        g_ww[(size_t)e * 8 + c] = w * win;
        kp |= (unsigned long long)kf << (8 * c);
    }
    g_kfp[e] = kp;
}

// Build per-(node,bin) entry lists: count -> scan -> fill. One block per node.
__global__ void k_build(const int* __restrict__ dst) {
    __shared__ int cnt[64];
    __shared__ int pos[64];
    int n = blockIdx.x, tid = threadIdx.x;   // 128
    int e0 = g_rowstart[n], e1 = g_rowstart[n + 1];
    if (tid < 64) cnt[tid] = 0;
    __syncthreads();
    for (int e = e0 + tid; e < e1; e += 128) {
        unsigned long long kp = g_kfp[e];
        #pragma unroll
        for (int j = 0; j < 8; j++)
            atomicAdd(&cnt[(int)((kp >> (8 * j)) & 63ull)], 1);
    }
    __syncthreads();
    if (tid == 0) {
        int run = 8 * e0;
        #pragma unroll 1
        for (int k = 0; k < 64; k++) {
            pos[k] = run;
            g_boff[n * 64 + k] = run;
            run += cnt[k];
        }
    }
    __syncthreads();
    for (int e = e0 + tid; e < e1; e += 128) {
        unsigned long long kp = g_kfp[e];
        int d = dst[e];
        const float4* wv = reinterpret_cast<const float4*>(g_ww + (size_t)e * 8);
        float4 wa = wv[0], wb = wv[1];
        float w[8] = {wa.x, wa.y, wa.z, wa.w, wb.x, wb.y, wb.z, wb.w};
        #pragma unroll
        for (int j = 0; j < 8; j++) {
            int k = (int)((kp >> (8 * j)) & 63ull);
            int idx = atomicAdd(&pos[k], 1);
            g_ent[idx] = make_int2(__float_as_int(w[j]), d);
        }
    }
}

// Pad conv0_w (64 bins x 13 cin x 64 cout) -> (64 x 16 x 64), zeros elsewhere.
__global__ void k_padw0(const float* __restrict__ w0) {
    int i = blockIdx.x * blockDim.x + threadIdx.x;
    if (i >= 1024 * 64) return;
    int o  = i & 63;
    int kc = i >> 6;
    int kf = kc >> 4, c = kc & 15;
    g_w0p[i] = (c < 13) ? w0[(kf * 13 + c) * 64 + o] : 0.f;
}

// Pre-convert a layer's W to tf32-rounded bits (done ONCE, not per GEMM block).
__global__ void k_cvtW(const float* __restrict__ W, int total4) {
    int i = blockIdx.x * blockDim.x + threadIdx.x;
    if (i >= total4) return;
    float4 x = reinterpret_cast<const float4*>(W)[i];
    uint4 h;
    h.x = f2tf32(x.x);
    h.y = f2tf32(x.y);
    h.z = f2tf32(x.z);
    h.w = f2tf32(x.w);
    reinterpret_cast<uint4*>(g_Whi)[i] = h;
}

// ---------------- feature prep (stride 16, zero-padded) ----------------
__global__ void k_prep0(const float* __restrict__ feats, float* __restrict__ inp) {
    int i = blockIdx.x * blockDim.x + threadIdx.x;
    if (i >= NN * 16) return;
    int n = i >> 4, c = i & 15;
    inp[i] = (c == 0) ? 1.0f : ((c < 13) ? feats[(size_t)n * 12 + (c - 1)] : 0.f);
}

// ---------------- bin-sorted gather: register accumulation, tf32-rounded out -
template<int CIN>
__global__ void k_gather(const float* __restrict__ inp) {
    int n    = blockIdx.x;
    int warp = threadIdx.x >> 5, lane = threadIdx.x & 31;
    const int2* __restrict__ ent = g_ent;
    if (CIN == 64) {
        // half-warp per bin: 16 lanes x float4 = 64 ch; 2 bins concurrent per warp
        int half = lane >> 4, hl = lane & 15;
        #pragma unroll 1
        for (int kb2 = warp * 16; kb2 < warp * 16 + 16; kb2 += 2) {
            int kb = kb2 + half;
            int s  = g_boff[n * 64 + kb];
            int se = g_boff[n * 64 + kb + 1];
            float4 a0 = {0.f, 0.f, 0.f, 0.f}, a1 = {0.f, 0.f, 0.f, 0.f};
            int i = s;
            for (; i + 1 < se; i += 2) {
                int2 e0 = ent[i], e1 = ent[i + 1];
                float w0 = __int_as_float(e0.x), w1 = __int_as_float(e1.x);
                float4 v0 = ((const float4*)(inp + (size_t)e0.y * 64))[hl];
                float4 v1 = ((const float4*)(inp + (size_t)e1.y * 64))[hl];
                a0.x = fmaf(w0, v0.x, a0.x); a0.y = fmaf(w0, v0.y, a0.y);
                a0.z = fmaf(w0, v0.z, a0.z); a0.w = fmaf(w0, v0.w, a0.w);
                a1.x = fmaf(w1, v1.x, a1.x); a1.y = fmaf(w1, v1.y, a1.y);
                a1.z = fmaf(w1, v1.z, a1.z); a1.w = fmaf(w1, v1.w, a1.w);
            }
            if (i < se) {
                int2 e0 = ent[i];
                float w0 = __int_as_float(e0.x);
                float4 v0 = ((const float4*)(inp + (size_t)e0.y * 64))[hl];
                a0.x = fmaf(w0, v0.x, a0.x); a0.y = fmaf(w0, v0.y, a0.y);
                a0.z = fmaf(w0, v0.z, a0.z); a0.w = fmaf(w0, v0.w, a0.w);
            }
            a0.x += a1.x; a0.y += a1.y; a0.z += a1.z; a0.w += a1.w;
            float4 r = make_float4(tf32r(a0.x), tf32r(a0.y), tf32r(a0.z), tf32r(a0.w));
            ((float4*)(g_B + (size_t)n * 64 * 64 + kb * 64))[hl] = r;
        }
    } else if (CIN == 96) {
        // 24 lanes x float4 = 96 ch; single dependent load per entry
        bool act = lane < 24;
        #pragma unroll 1
        for (int kb = warp * 16; kb < warp * 16 + 16; kb++) {
            int s  = g_boff[n * 64 + kb];
            int se = g_boff[n * 64 + kb + 1];
            float4 a0 = {0.f, 0.f, 0.f, 0.f}, a1 = {0.f, 0.f, 0.f, 0.f};
            int i = s;
            for (; i + 1 < se; i += 2) {
                int2 e0 = ent[i], e1 = ent[i + 1];
                float w0 = __int_as_float(e0.x), w1 = __int_as_float(e1.x);
                if (act) {
                    float4 v0 = ((const float4*)(inp + (size_t)e0.y * 96))[lane];
                    float4 v1 = ((const float4*)(inp + (size_t)e1.y * 96))[lane];
                    a0.x = fmaf(w0, v0.x, a0.x); a0.y = fmaf(w0, v0.y, a0.y);
                    a0.z = fmaf(w0, v0.z, a0.z); a0.w = fmaf(w0, v0.w, a0.w);
                    a1.x = fmaf(w1, v1.x, a1.x); a1.y = fmaf(w1, v1.y, a1.y);
                    a1.z = fmaf(w1, v1.z, a1.z); a1.w = fmaf(w1, v1.w, a1.w);
                }
            }
            if (i < se) {
                int2 e0 = ent[i];
                float w0 = __int_as_float(e0.x);
                if (act) {
                    float4 v0 = ((const float4*)(inp + (size_t)e0.y * 96))[lane];
                    a0.x = fmaf(w0, v0.x, a0.x); a0.y = fmaf(w0, v0.y, a0.y);
                    a0.z = fmaf(w0, v0.z, a0.z); a0.w = fmaf(w0, v0.w, a0.w);
                }
            }
            if (act) {
                a0.x += a1.x; a0.y += a1.y; a0.z += a1.z; a0.w += a1.w;
                float4 r = make_float4(tf32r(a0.x), tf32r(a0.y), tf32r(a0.z), tf32r(a0.w));
                ((float4*)(g_B + (size_t)n * 64 * 96 + kb * 96))[lane] = r;
            }
        }
    } else {  // CIN == 16: quarter-warps process 4 entries concurrently
        #pragma unroll 1
        for (int kb = warp * 16; kb < warp * 16 + 16; kb++) {
            int s  = g_boff[n * 64 + kb];
            int se = g_boff[n * 64 + kb + 1];
            int sub = lane >> 3, slot = lane & 7;
            float2 a = {0.f, 0.f};
            for (int i = s + sub; i < se; i += 4) {
                int2 ev = ent[i];
                float w = __int_as_float(ev.x);
                float2 v = ((const float2*)(inp + (size_t)ev.y * 16))[slot];
                a.x = fmaf(w, v.x, a.x); a.y = fmaf(w, v.y, a.y);
            }
            a.x += __shfl_xor_sync(0xffffffffu, a.x, 8);
            a.y += __shfl_xor_sync(0xffffffffu, a.y, 8);
            a.x += __shfl_xor_sync(0xffffffffu, a.x, 16);
            a.y += __shfl_xor_sync(0xffffffffu, a.y, 16);
            if (lane < 8)
                ((float2*)(g_B + (size_t)n * 64 * 16 + kb * 16))[slot] =
                    make_float2(tf32r(a.x), tf32r(a.y));
        }
    }
}

// ---------------- 1-pass TF32 GEMM: C[M,64] = A(tf32)[M,Kd] @ W(tf32) --------
// Both operands pre-rounded to tf32 -> no conversion anywhere in the hot loop.
__global__ void k_gemm_tf32(const float* __restrict__ A,
                            float* __restrict__ C, int M, int Kd) {
    __shared__ uint32_t Ahi[32 * 72];                 // [k][m], stride 72
    __shared__ uint32_t Whi[32 * 72];                 // [k][n], stride 72
    int tid  = threadIdx.x;          // 128
    int m0   = blockIdx.x * 64;
    int warp = tid >> 5, lane = tid & 31;
    int g = lane >> 2, tq = lane & 3;
    int wm = (warp >> 1) * 32, wn = (warp & 1) * 32;
    float acc[2][4][4];
    #pragma unroll
    for (int mi = 0; mi < 2; mi++)
        #pragma unroll
        for (int ni = 0; ni < 4; ni++)
            #pragma unroll
            for (int q = 0; q < 4; q++) acc[mi][ni][q] = 0.f;

    // W loader indices: 128 threads x 16 words = 2048 = 32 k-rows x 64 cols.
    int wkk = tid >> 2;              // 0..31  (k-row)
    int wnq = (tid & 3) * 16;        // 0,16,32,48 (col quarter)

    for (int k0 = 0; k0 < Kd; k0 += 32) {
        #pragma unroll
        for (int i = 0; i < 4; i++) {
            int fi  = tid + 128 * i;
            int row = fi >> 3;
            int kq  = (fi & 7) * 4;
            uint4 v = make_uint4(0u, 0u, 0u, 0u);
            if (m0 + row < M)
                v = *reinterpret_cast<const uint4*>(
                        reinterpret_cast<const uint32_t*>(A) + (size_t)(m0 + row) * Kd + k0 + kq);
            Ahi[(kq + 0) * 72 + row] = v.x;
            Ahi[(kq + 1) * 72 + row] = v.y;
            Ahi[(kq + 2) * 72 + row] = v.z;
            Ahi[(kq + 3) * 72 + row] = v.w;
        }
        {
            size_t off = (size_t)(k0 + wkk) * 64 + wnq;
            uint4 hv0 = *reinterpret_cast<const uint4*>(g_Whi + off);
            uint4 hv1 = *reinterpret_cast<const uint4*>(g_Whi + off + 4);
            uint4 hv2 = *reinterpret_cast<const uint4*>(g_Whi + off + 8);
            uint4 hv3 = *reinterpret_cast<const uint4*>(g_Whi + off + 12);
            uint32_t* wr = &Whi[wkk * 72 + wnq];
            wr[0]  = hv0.x; wr[1]  = hv0.y; wr[2]  = hv0.z; wr[3]  = hv0.w;
            wr[4]  = hv1.x; wr[5]  = hv1.y; wr[6]  = hv1.z; wr[7]  = hv1.w;
            wr[8]  = hv2.x; wr[9]  = hv2.y; wr[10] = hv2.z; wr[11] = hv2.w;
            wr[12] = hv3.x; wr[13] = hv3.y; wr[14] = hv3.z; wr[15] = hv3.w;
        }
        __syncthreads();
        #pragma unroll
        for (int ks = 0; ks < 4; ks++) {
            int k8 = ks * 8;
            uint32_t ah[2][4], bh[4][2];
            #pragma unroll
            for (int mi = 0; mi < 2; mi++) {
                int m = wm + mi * 16 + g;
                ah[mi][0] = Ahi[(k8 + tq) * 72 + m];
                ah[mi][1] = Ahi[(k8 + tq) * 72 + m + 8];
                ah[mi][2] = Ahi[(k8 + tq + 4) * 72 + m];
                ah[mi][3] = Ahi[(k8 + tq + 4) * 72 + m + 8];
            }
            #pragma unroll
            for (int ni = 0; ni < 4; ni++) {
                int n = wn + ni * 8 + g;
                bh[ni][0] = Whi[(k8 + tq) * 72 + n];
                bh[ni][1] = Whi[(k8 + tq + 4) * 72 + n];
            }
            #pragma unroll
            for (int mi = 0; mi < 2; mi++)
                #pragma unroll
                for (int ni = 0; ni < 4; ni++)
                    mma_tf32(acc[mi][ni], ah[mi], bh[ni]);
        }
        __syncthreads();
    }
    #pragma unroll
    for (int mi = 0; mi < 2; mi++) {
        int r0 = m0 + wm + mi * 16 + g;
        int r1 = r0 + 8;
        #pragma unroll
        for (int ni = 0; ni < 4; ni++) {
            int c = wn + ni * 8 + 2 * tq;
            if (r0 < M) {
                C[(size_t)r0 * 64 + c]     = acc[mi][ni][0];
                C[(size_t)r0 * 64 + c + 1] = acc[mi][ni][1];
            }
            if (r1 < M) {
                C[(size_t)r1 * 64 + c]     = acc[mi][ni][2];
                C[(size_t)r1 * 64 + c + 1] = acc[mi][ni][3];
            }
        }
    }
}

// ---------------- skinny GEMV (layer 3): y[M,3] = A[M,Kd] @ W3[Kd,3] ---------
__global__ void k_gemv3(const float* __restrict__ A, const float* __restrict__ W3,
                        float* __restrict__ y, int M, int Kd) {
    int gw   = (blockIdx.x * blockDim.x + threadIdx.x) >> 5;
    int lane = threadIdx.x & 31;
    if (gw >= M) return;
    const float4* a4 = (const float4*)(A + (size_t)gw * Kd);
    float s0 = 0.f, s1 = 0.f, s2 = 0.f;
    for (int k4 = lane; k4 < Kd / 4; k4 += 32) {
        float4 av = a4[k4];
        int k = k4 * 4;
        s0 = fmaf(av.x, W3[k * 3 + 0], s0);
        s1 = fmaf(av.x, W3[k * 3 + 1], s1);
        s2 = fmaf(av.x, W3[k * 3 + 2], s2);
        s0 = fmaf(av.y, W3[k * 3 + 3], s0);
        s1 = fmaf(av.y, W3[k * 3 + 4], s1);
        s2 = fmaf(av.y, W3[k * 3 + 5], s2);
        s0 = fmaf(av.z, W3[k * 3 + 6], s0);
        s1 = fmaf(av.z, W3[k * 3 + 7], s1);
        s2 = fmaf(av.z, W3[k * 3 + 8], s2);
        s0 = fmaf(av.w, W3[k * 3 + 9], s0);
        s1 = fmaf(av.w, W3[k * 3 + 10], s1);
        s2 = fmaf(av.w, W3[k * 3 + 11], s2);
    }
    #pragma unroll
    for (int off = 16; off; off >>= 1) {
        s0 += __shfl_xor_sync(0xffffffffu, s0, off);
        s1 += __shfl_xor_sync(0xffffffffu, s1, off);
        s2 += __shfl_xor_sync(0xffffffffu, s2, off);
    }
    if (lane == 0) {
        y[(size_t)gw * 3 + 0] = s0;
        y[(size_t)gw * 3 + 1] = s1;
        y[(size_t)gw * 3 + 2] = s2;
    }
}

// ---------------- epilogue: conv bias + dense + residual + fused relu --------
__global__ void k_combine(const float* __restrict__ y, const float* __restrict__ cb,
                          const float* __restrict__ dw, const float* __restrict__ db,
                          const float* __restrict__ inp, int cin, int instride,
                          const float* __restrict__ xold, int xold_stride,
                          float* __restrict__ out, float* __restrict__ relu_out,
                          int out_stride, int out_rows,
                          int conv_cols, int dense_cols, int dense_off, float scale) {
    __shared__ float si[96];
    int n = blockIdx.x;
    int o = threadIdx.x;  // 96
    if (o < cin) si[o] = inp[(size_t)n * instride + o];
    __syncthreads();
    int width = dense_off + dense_cols;
    if (conv_cols > width) width = conv_cols;
    if (o >= width || n >= out_rows) return;
    float v = 0.f;
    if (o < conv_cols) v = y[(size_t)n * conv_cols + o] + cb[o];
    if (o >= dense_off) {
        int od = o - dense_off;
        if (od < dense_cols) {
            float s2 = db[od];
            for (int i = 0; i < cin; i++) s2 = fmaf(si[i], dw[i * dense_cols + od], s2);
            v += s2;
        }
    }
    if (xold) v += xold[(size_t)n * xold_stride + o];
    v *= scale;
    out[(size_t)n * out_stride + o] = v;
    if (relu_out) relu_out[(size_t)n * out_stride + o] = fmaxf(v, 0.f);
}

// ---------------- launch ----------------
extern "C" void kernel_launch(void* const* d_in, const int* in_sizes, int n_in,
                              void* d_out, int out_size) {
    const float* pos   = (const float*)d_in[0];
    const float* feats = (const float*)d_in[1];
    const int*   esrc  = (const int*)d_in[2];
    const int*   edst  = (const int*)d_in[3];
    const float* c0w = (const float*)d_in[4];
    const float* c0b = (const float*)d_in[5];
    const float* d0w = (const float*)d_in[6];
    const float* d0b = (const float*)d_in[7];
    const float* c1w = (const float*)d_in[8];
    const float* c1b = (const float*)d_in[9];
    const float* d1w = (const float*)d_in[10];
    const float* d1b = (const float*)d_in[11];
    const float* c2w = (const float*)d_in[12];
    const float* c2b = (const float*)d_in[13];
    const float* d2w = (const float*)d_in[14];
    const float* d2b = (const float*)d_in[15];
    const float* c3w = (const float*)d_in[16];
    const float* c3b = (const float*)d_in[17];
    const float* d3w = (const float*)d_in[18];
    const float* d3b = (const float*)d_in[19];
    float* out = (float*)d_out;

    void *pB, *pA, *pBB, *pI, *pI2, *pY, *pW0;
    cudaGetSymbolAddress(&pB,  g_B);
    cudaGetSymbolAddress(&pA,  g_bufA);
    cudaGetSymbolAddress(&pBB, g_bufB);
    cudaGetSymbolAddress(&pI,  g_inp);
    cudaGetSymbolAddress(&pI2, g_inp2);
    cudaGetSymbolAddress(&pY,  g_y);
    cudaGetSymbolAddress(&pW0, g_w0p);
    float* B    = (float*)pB;
    float* bufA = (float*)pA;
    float* bufB = (float*)pBB;
    float* inp  = (float*)pI;
    float* inp2 = (float*)pI2;
    float* y    = (float*)pY;
    float* w0p  = (float*)pW0;

    const int EB = (EPAD + 255) / 256;
    const int GT = (NN + 63) / 64;   // 313 GEMM M-tiles

    // edge preprocessing (shared across all 4 conv layers)
    k_findpad<<<1, 1>>>(edst);
    k_rowstart<<<(NN + 2 + 255) / 256, 256>>>(esrc);
    k_geom<<<EB, 256>>>(pos, esrc, edst);
    k_build<<<NN, 128>>>(edst);
    k_padw0<<<(1024 * 64 + 255) / 256, 256>>>(c0w);

    // ---- layer 0 (cin 13 padded to 16) ----
    k_prep0<<<(NN * 16 + 255) / 256, 256>>>(feats, inp);
    k_gather<16><<<NN, 128>>>(inp);
    k_cvtW<<<(1024 * 16 + 255) / 256, 256>>>(w0p, 1024 * 16);
    k_gemm_tf32<<<GT, 128>>>(B, y, NN, 64 * 16);
    k_combine<<<NN, 96>>>(y, c0b, d0w, d0b, inp, 13, 16, nullptr, 0,
                          bufA, inp2, 96, NN, 64, 32, 64, 1.f);
    // ---- layer 1 ----
    k_gather<96><<<NN, 128>>>(inp2);
    k_cvtW<<<(6144 * 16 + 255) / 256, 256>>>(c1w, 6144 * 16);
    k_gemm_tf32<<<GT, 128>>>(B, y, NN, 64 * 96);
    k_combine<<<NN, 96>>>(y, c1b, d1w, d1b, inp2, 96, 96, nullptr, 0,
                          bufB, inp, 64, NN, 64, 64, 0, 1.f);
    // ---- layer 2 (residual) ----
    k_gather<64><<<NN, 128>>>(inp);
    k_cvtW<<<(4096 * 16 + 255) / 256, 256>>>(c2w, 4096 * 16);
    k_gemm_tf32<<<GT, 128>>>(B, y, NN, 64 * 64);
    k_combine<<<NN, 96>>>(y, c2b, d2w, d2b, inp, 64, 64, bufB, 64,
                          bufA, inp2, 64, NN, 64, 64, 0, 1.f);
    // ---- layer 3 (output, /128, first 20000 rows) ----
    k_gather<64><<<NN, 128>>>(inp2);
    k_gemv3<<<(NN * 32 + 255) / 256, 256>>>(B, c3w, y, NN, 64 * 64);
    k_combine<<<NREAL, 96>>>(y, c3b, d3w, d3b, inp2, 64, 64, nullptr, 0,
                             out, nullptr, 3, NREAL, 3, 3, 0, 1.f / 128.f);
}

// round 17
// speedup vs baseline: 1.5398x; 1.0293x over previous
#include <cuda_runtime.h>
#include <cuda_fp16.h>
#include <math.h>
#include <stdint.h>

#define NN     20001
#define NREAL  20000
#define EPAD   1200000
#define RADIUS_F 0.1125f

// ---------------- scratch (device globals; no allocations) ----------------
__device__ float g_B[(size_t)NN * 64 * 96];        // bin accumulator (tf32-rounded), max cin=96
__device__ float g_bufA[(size_t)NN * 96];
__device__ float g_bufB[(size_t)NN * 96];
__device__ float g_inp[(size_t)NN * 96];
__device__ float g_inp2[(size_t)NN * 96];
__device__ __half g_hf[(size_t)NN * 96];           // fp16 feature stream for gathers
__device__ float g_y[(size_t)NN * 64];
__device__ float g_ww[(size_t)EPAD * 8];           // win * trilinear weight per corner
__device__ unsigned long long g_kfp[EPAD];         // 8 packed 6-bit kernel indices
__device__ int2 g_ent[(size_t)EPAD * 8];           // (weight bits, dst) sorted by (node,bin)
__device__ int g_boff[NN * 64 + 1];                // per-(node,bin) entry offsets
__device__ float g_w0p[1024 * 64];                 // conv0_w padded cin 13->16
__device__ uint32_t g_Whi[6144 * 64];              // tf32-rounded current layer W (bits)
__device__ int g_rowstart[NN + 2];

// ---------------- helpers ----------------
__device__ __forceinline__ float fsign(float v) {
    return (v > 0.f) ? 1.f : ((v < 0.f) ? -1.f : 0.f);
}

__device__ __forceinline__ uint32_t f2tf32(float x) {
    uint32_t r;
    asm("cvt.rna.tf32.f32 %0, %1;" : "=r"(r) : "f"(x));
    return r;
}

__device__ __forceinline__ float tf32r(float x) {
    return __uint_as_float(f2tf32(x));
}

__device__ __forceinline__ void mma_tf32(float* d, const uint32_t* a, const uint32_t* b) {
    asm volatile(
        "mma.sync.aligned.m16n8k8.row.col.f32.tf32.tf32.f32 "
        "{%0,%1,%2,%3}, {%4,%5,%6,%7}, {%8,%9}, {%0,%1,%2,%3};"
        : "+f"(d[0]), "+f"(d[1]), "+f"(d[2]), "+f"(d[3])
        : "r"(a[0]), "r"(a[1]), "r"(a[2]), "r"(a[3]), "r"(b[0]), "r"(b[1]));
}

__device__ __forceinline__ void ball_to_cube(float x, float y, float z,
                                             float& a, float& b, float& zc) {
    const float eps = 1e-9f;
    float sq   = x * x + y * y + z * z;
    float norm = sqrtf(sq + eps);
    float rxy2 = x * x + y * y;
    bool  polar = 1.25f * z * z > rxy2;
    float s = polar ? sqrtf(3.f * norm / (norm + fabsf(z) + eps))
                    : norm / sqrtf(rxy2 + eps);
    float xc = x * s;
    float yc = y * s;
    float zz = polar ? fsign(z) * norm : 1.5f * z;
    if (sq < 1e-12f) { xc = 0.f; yc = 0.f; zz = 0.f; }
    float r  = sqrtf(xc * xc + yc * yc + eps);
    bool  c1 = fabsf(xc) >= fabsf(yc);
    float xs = (fabsf(xc) < eps) ? eps : xc;
    float ys = (fabsf(yc) < eps) ? eps : yc;
    const float fop = 1.27323954473516268615f;  // 4/pi
    float av = c1 ? fsign(xc) * r : fsign(yc) * r * fop * atanf(xc / ys);
    float bv = c1 ? fsign(xc) * r * fop * atanf(yc / xs) : fsign(yc) * r;
    if (xc * xc + yc * yc < 1e-12f) { av = 0.f; bv = 0.f; }
    a = av; b = bv; zc = zz;
}

// ---------------- fused pre: findpad + rowstart + prep0 (fp32 + fp16) -------
__global__ void k_pre(const float* __restrict__ feats,
                      const int* __restrict__ src, const int* __restrict__ dst,
                      float* __restrict__ inp, __half* __restrict__ hinp) {
    int i = blockIdx.x * blockDim.x + threadIdx.x;
    if (i <= NN) {
        // local binary search for first pad edge (dst == NREAL at the tail)
        int lo = 0, hi = EPAD;
        while (lo < hi) {
            int mid = (lo + hi) >> 1;
            if (dst[mid] < NREAL) lo = mid + 1; else hi = mid;
        }
        int E = lo;
        if (i == 0) g_boff[NN * 64] = 8 * E;   // sentinel
        int l2 = 0, h2 = E;
        while (l2 < h2) {
            int mid = (l2 + h2) >> 1;
            if (src[mid] < i) l2 = mid + 1; else h2 = mid;
        }
        g_rowstart[i] = l2;
    }
    if (i < NN * 16) {
        int n = i >> 4, c = i & 15;
        float v = (c == 0) ? 1.0f : ((c < 13) ? feats[(size_t)n * 12 + (c - 1)] : 0.f);
        inp[i]  = v;
        hinp[i] = __float2half(v);
    }
}

__global__ void k_geom(const float* __restrict__ pos,
                       const int* __restrict__ src,
                       const int* __restrict__ dst) {
    int e = blockIdx.x * blockDim.x + threadIdx.x;
    if (e >= EPAD) return;
    int d = dst[e];
    if (d >= NREAL) return;  // pad edge (win == 0)
    int s = src[e];
    float ox = (pos[(size_t)d * 3 + 0] - pos[(size_t)s * 3 + 0]) * (1.f / RADIUS_F);
    float oy = (pos[(size_t)d * 3 + 1] - pos[(size_t)s * 3 + 1]) * (1.f / RADIUS_F);
    float oz = (pos[(size_t)d * 3 + 2] - pos[(size_t)s * 3 + 2]) * (1.f / RADIUS_F);
    float r2 = ox * ox + oy * oy + oz * oz;
    float u  = 1.f - r2;
    float win = u * u * u;
    win = fminf(fmaxf(win, 0.f), 1.f);
    float ca, cb, cc;
    ball_to_cube(ox, oy, oz, ca, cb, cc);
    float gx = fminf(fmaxf((ca * 0.5f + 0.5f) * 3.f, 0.f), 3.f);
    float gy = fminf(fmaxf((cb * 0.5f + 0.5f) * 3.f, 0.f), 3.f);
    float gz = fminf(fmaxf((cc * 0.5f + 0.5f) * 3.f, 0.f), 3.f);
    float fx = floorf(gx), fy = floorf(gy), fz = floorf(gz);
    float tx = gx - fx, ty = gy - fy, tz = gz - fz;
    int ix0 = min((int)fx, 3), ix1 = min((int)fx + 1, 3);
    int iy0 = min((int)fy, 3), iy1 = min((int)fy + 1, 3);
    int iz0 = min((int)fz, 3), iz1 = min((int)fz + 1, 3);
    unsigned long long kp = 0;
    #pragma unroll
    for (int c = 0; c < 8; c++) {
        int bx = (c >> 2) & 1, by = (c >> 1) & 1, bz = c & 1;
        int kf = ((bx ? ix1 : ix0) * 4 + (by ? iy1 : iy0)) * 4 + (bz ? iz1 : iz0);
        float w = (bx ? tx : 1.f - tx) * (by ? ty : 1.f - ty) * (bz ? tz : 1.f - tz);
        g_ww[(size_t)e * 8 + c] = w * win;
        kp |= (unsigned long long)kf << (8 * c);
    }
    g_kfp[e] = kp;
}

// Build per-(node,bin) entry lists: count -> scan -> fill. One block per node.
__global__ void k_build(const int* __restrict__ dst) {
    __shared__ int cnt[64];
    __shared__ int pos[64];
    int n = blockIdx.x, tid = threadIdx.x;   // 128
    int e0 = g_rowstart[n], e1 = g_rowstart[n + 1];
    if (tid < 64) cnt[tid] = 0;
    __syncthreads();
    for (int e = e0 + tid; e < e1; e += 128) {
        unsigned long long kp = g_kfp[e];
        #pragma unroll
        for (int j = 0; j < 8; j++)
            atomicAdd(&cnt[(int)((kp >> (8 * j)) & 63ull)], 1);
    }
    __syncthreads();
    if (tid == 0) {
        int run = 8 * e0;
        #pragma unroll 1
        for (int k = 0; k < 64; k++) {
            pos[k] = run;
            g_boff[n * 64 + k] = run;
            run += cnt[k];
        }
    }
    __syncthreads();
    for (int e = e0 + tid; e < e1; e += 128) {
        unsigned long long kp = g_kfp[e];
        int d = dst[e];
        const float4* wv = reinterpret_cast<const float4*>(g_ww + (size_t)e * 8);
        float4 wa = wv[0], wb = wv[1];
        float w[8] = {wa.x, wa.y, wa.z, wa.w, wb.x, wb.y, wb.z, wb.w};
        #pragma unroll
        for (int j = 0; j < 8; j++) {
            int k = (int)((kp >> (8 * j)) & 63ull);
            int idx = atomicAdd(&pos[k], 1);
            g_ent[idx] = make_int2(__float_as_int(w[j]), d);
        }
    }
}

// Pad conv0_w (64 bins x 13 cin x 64 cout) -> (64 x 16 x 64), zeros elsewhere.
__global__ void k_padw0(const float* __restrict__ w0) {
    int i = blockIdx.x * blockDim.x + threadIdx.x;
    if (i >= 1024 * 64) return;
    int o  = i & 63;
    int kc = i >> 6;
    int kf = kc >> 4, c = kc & 15;
    g_w0p[i] = (c < 13) ? w0[(kf * 13 + c) * 64 + o] : 0.f;
}

// Pre-convert a layer's W to tf32-rounded bits (done ONCE, not per GEMM block).
__global__ void k_cvtW(const float* __restrict__ W, int total4) {
    int i = blockIdx.x * blockDim.x + threadIdx.x;
    if (i >= total4) return;
    float4 x = reinterpret_cast<const float4*>(W)[i];
    uint4 h;
    h.x = f2tf32(x.x);
    h.y = f2tf32(x.y);
    h.z = f2tf32(x.z);
    h.w = f2tf32(x.w);
    reinterpret_cast<uint4*>(g_Whi)[i] = h;
}

// ---------------- bin-sorted gather (fp16 feature stream, fp32 accumulate) ---
template<int CIN>
__global__ void k_gather(const __half* __restrict__ hf) {
    int n    = blockIdx.x;
    int warp = threadIdx.x >> 5, lane = threadIdx.x & 31;
    const int2* __restrict__ ent = g_ent;
    if (CIN == 64) {
        // half-warp per bin: 16 lanes x 4 ch (uint2 of halves); 2 bins/warp concurrent
        int half = lane >> 4, hl = lane & 15;
        #pragma unroll 1
        for (int kb2 = warp * 16; kb2 < warp * 16 + 16; kb2 += 2) {
            int kb = kb2 + half;
            int s  = g_boff[n * 64 + kb];
            int se = g_boff[n * 64 + kb + 1];
            float4 a0 = {0.f, 0.f, 0.f, 0.f}, a1 = {0.f, 0.f, 0.f, 0.f};
            int i = s;
            for (; i + 1 < se; i += 2) {
                int2 e0 = ent[i], e1 = ent[i + 1];
                float w0 = __int_as_float(e0.x), w1 = __int_as_float(e1.x);
                uint2 h0 = ((const uint2*)(hf + (size_t)e0.y * 64))[hl];
                uint2 h1 = ((const uint2*)(hf + (size_t)e1.y * 64))[hl];
                float2 p00 = __half22float2(*(__half2*)&h0.x);
                float2 p01 = __half22float2(*(__half2*)&h0.y);
                float2 p10 = __half22float2(*(__half2*)&h1.x);
                float2 p11 = __half22float2(*(__half2*)&h1.y);
                a0.x = fmaf(w0, p00.x, a0.x); a0.y = fmaf(w0, p00.y, a0.y);
                a0.z = fmaf(w0, p01.x, a0.z); a0.w = fmaf(w0, p01.y, a0.w);
                a1.x = fmaf(w1, p10.x, a1.x); a1.y = fmaf(w1, p10.y, a1.y);
                a1.z = fmaf(w1, p11.x, a1.z); a1.w = fmaf(w1, p11.y, a1.w);
            }
            if (i < se) {
                int2 e0 = ent[i];
                float w0 = __int_as_float(e0.x);
                uint2 h0 = ((const uint2*)(hf + (size_t)e0.y * 64))[hl];
                float2 p00 = __half22float2(*(__half2*)&h0.x);
                float2 p01 = __half22float2(*(__half2*)&h0.y);
                a0.x = fmaf(w0, p00.x, a0.x); a0.y = fmaf(w0, p00.y, a0.y);
                a0.z = fmaf(w0, p01.x, a0.z); a0.w = fmaf(w0, p01.y, a0.w);
            }
            a0.x += a1.x; a0.y += a1.y; a0.z += a1.z; a0.w += a1.w;
            float4 r = make_float4(tf32r(a0.x), tf32r(a0.y), tf32r(a0.z), tf32r(a0.w));
            ((float4*)(g_B + (size_t)n * 64 * 64 + kb * 64))[hl] = r;
        }
    } else if (CIN == 96) {
        // 24 lanes x 4 ch (uint2 of halves)
        bool act = lane < 24;
        #pragma unroll 1
        for (int kb = warp * 16; kb < warp * 16 + 16; kb++) {
            int s  = g_boff[n * 64 + kb];
            int se = g_boff[n * 64 + kb + 1];
            float4 a0 = {0.f, 0.f, 0.f, 0.f}, a1 = {0.f, 0.f, 0.f, 0.f};
            int i = s;
            for (; i + 1 < se; i += 2) {
                int2 e0 = ent[i], e1 = ent[i + 1];
                float w0 = __int_as_float(e0.x), w1 = __int_as_float(e1.x);
                if (act) {
                    uint2 h0 = ((const uint2*)(hf + (size_t)e0.y * 96))[lane];
                    uint2 h1 = ((const uint2*)(hf + (size_t)e1.y * 96))[lane];
                    float2 p00 = __half22float2(*(__half2*)&h0.x);
                    float2 p01 = __half22float2(*(__half2*)&h0.y);
                    float2 p10 = __half22float2(*(__half2*)&h1.x);
                    float2 p11 = __half22float2(*(__half2*)&h1.y);
                    a0.x = fmaf(w0, p00.x, a0.x); a0.y = fmaf(w0, p00.y, a0.y);
                    a0.z = fmaf(w0, p01.x, a0.z); a0.w = fmaf(w0, p01.y, a0.w);
                    a1.x = fmaf(w1, p10.x, a1.x); a1.y = fmaf(w1, p10.y, a1.y);
                    a1.z = fmaf(w1, p11.x, a1.z); a1.w = fmaf(w1, p11.y, a1.w);
                }
            }
            if (i < se) {
                int2 e0 = ent[i];
                float w0 = __int_as_float(e0.x);
                if (act) {
                    uint2 h0 = ((const uint2*)(hf + (size_t)e0.y * 96))[lane];
                    float2 p00 = __half22float2(*(__half2*)&h0.x);
                    float2 p01 = __half22float2(*(__half2*)&h0.y);
                    a0.x = fmaf(w0, p00.x, a0.x); a0.y = fmaf(w0, p00.y, a0.y);
                    a0.z = fmaf(w0, p01.x, a0.z); a0.w = fmaf(w0, p01.y, a0.w);
                }
            }
            if (act) {
                a0.x += a1.x; a0.y += a1.y; a0.z += a1.z; a0.w += a1.w;
                float4 r = make_float4(tf32r(a0.x), tf32r(a0.y), tf32r(a0.z), tf32r(a0.w));
                ((float4*)(g_B + (size_t)n * 64 * 96 + kb * 96))[lane] = r;
            }
        }
    } else {  // CIN == 16: quarter-warps process 4 entries concurrently
        #pragma unroll 1
        for (int kb = warp * 16; kb < warp * 16 + 16; kb++) {
            int s  = g_boff[n * 64 + kb];
            int se = g_boff[n * 64 + kb + 1];
            int sub = lane >> 3, slot = lane & 7;
            float2 a = {0.f, 0.f};
            for (int i = s + sub; i < se; i += 4) {
                int2 ev = ent[i];
                float w = __int_as_float(ev.x);
                uint32_t hv = ((const uint32_t*)(hf + (size_t)ev.y * 16))[slot];
                float2 v = __half22float2(*(__half2*)&hv);
                a.x = fmaf(w, v.x, a.x); a.y = fmaf(w, v.y, a.y);
            }
            a.x += __shfl_xor_sync(0xffffffffu, a.x, 8);
            a.y += __shfl_xor_sync(0xffffffffu, a.y, 8);
            a.x += __shfl_xor_sync(0xffffffffu, a.x, 16);
            a.y += __shfl_xor_sync(0xffffffffu, a.y, 16);
            if (lane < 8)
                ((float2*)(g_B + (size_t)n * 64 * 16 + kb * 16))[slot] =
                    make_float2(tf32r(a.x), tf32r(a.y));
        }
    }
}

// ---------------- 1-pass TF32 GEMM: C[M,64] = A(tf32)[M,Kd] @ W(tf32) --------
__global__ void k_gemm_tf32(const float* __restrict__ A,
                            float* __restrict__ C, int M, int Kd) {
    __shared__ uint32_t Ahi[32 * 72];                 // [k][m], stride 72
    __shared__ uint32_t Whi[32 * 72];                 // [k][n], stride 72
    int tid  = threadIdx.x;          // 128
    int m0   = blockIdx.x * 64;
    int warp = tid >> 5, lane = tid & 31;
    int g = lane >> 2, tq = lane & 3;
    int wm = (warp >> 1) * 32, wn = (warp & 1) * 32;
    float acc[2][4][4];
    #pragma unroll
    for (int mi = 0; mi < 2; mi++)
        #pragma unroll
        for (int ni = 0; ni < 4; ni++)
            #pragma unroll
            for (int q = 0; q < 4; q++) acc[mi][ni][q] = 0.f;

    int wkk = tid >> 2;              // 0..31  (k-row)
    int wnq = (tid & 3) * 16;        // 0,16,32,48 (col quarter)

    for (int k0 = 0; k0 < Kd; k0 += 32) {
        #pragma unroll
        for (int i = 0; i < 4; i++) {
            int fi  = tid + 128 * i;
            int row = fi >> 3;
            int kq  = (fi & 7) * 4;
            uint4 v = make_uint4(0u, 0u, 0u, 0u);
            if (m0 + row < M)
                v = *reinterpret_cast<const uint4*>(
                        reinterpret_cast<const uint32_t*>(A) + (size_t)(m0 + row) * Kd + k0 + kq);
            Ahi[(kq + 0) * 72 + row] = v.x;
            Ahi[(kq + 1) * 72 + row] = v.y;
            Ahi[(kq + 2) * 72 + row] = v.z;
            Ahi[(kq + 3) * 72 + row] = v.w;
        }
        {
            size_t off = (size_t)(k0 + wkk) * 64 + wnq;
            uint4 hv0 = *reinterpret_cast<const uint4*>(g_Whi + off);
            uint4 hv1 = *reinterpret_cast<const uint4*>(g_Whi + off + 4);
            uint4 hv2 = *reinterpret_cast<const uint4*>(g_Whi + off + 8);
            uint4 hv3 = *reinterpret_cast<const uint4*>(g_Whi + off + 12);
            uint32_t* wr = &Whi[wkk * 72 + wnq];
            wr[0]  = hv0.x; wr[1]  = hv0.y; wr[2]  = hv0.z; wr[3]  = hv0.w;
            wr[4]  = hv1.x; wr[5]  = hv1.y; wr[6]  = hv1.z; wr[7]  = hv1.w;
            wr[8]  = hv2.x; wr[9]  = hv2.y; wr[10] = hv2.z; wr[11] = hv2.w;
            wr[12] = hv3.x; wr[13] = hv3.y; wr[14] = hv3.z; wr[15] = hv3.w;
        }
        __syncthreads();
        #pragma unroll
        for (int ks = 0; ks < 4; ks++) {
            int k8 = ks * 8;
            uint32_t ah[2][4], bh[4][2];
            #pragma unroll
            for (int mi = 0; mi < 2; mi++) {
                int m = wm + mi * 16 + g;
                ah[mi][0] = Ahi[(k8 + tq) * 72 + m];
                ah[mi][1] = Ahi[(k8 + tq) * 72 + m + 8];
                ah[mi][2] = Ahi[(k8 + tq + 4) * 72 + m];
                ah[mi][3] = Ahi[(k8 + tq + 4) * 72 + m + 8];
            }
            #pragma unroll
            for (int ni = 0; ni < 4; ni++) {
                int n = wn + ni * 8 + g;
                bh[ni][0] = Whi[(k8 + tq) * 72 + n];
                bh[ni][1] = Whi[(k8 + tq + 4) * 72 + n];
            }
            #pragma unroll
            for (int mi = 0; mi < 2; mi++)
                #pragma unroll
                for (int ni = 0; ni < 4; ni++)
                    mma_tf32(acc[mi][ni], ah[mi], bh[ni]);
        }
        __syncthreads();
    }
    #pragma unroll
    for (int mi = 0; mi < 2; mi++) {
        int r0 = m0 + wm + mi * 16 + g;
        int r1 = r0 + 8;
        #pragma unroll
        for (int ni = 0; ni < 4; ni++) {
            int c = wn + ni * 8 + 2 * tq;
            if (r0 < M) {
                C[(size_t)r0 * 64 + c]     = acc[mi][ni][0];
                C[(size_t)r0 * 64 + c + 1] = acc[mi][ni][1];
            }
            if (r1 < M) {
                C[(size_t)r1 * 64 + c]     = acc[mi][ni][2];
                C[(size_t)r1 * 64 + c + 1] = acc[mi][ni][3];
            }
        }
    }
}

// ---------------- skinny GEMV (layer 3): y[M,3] = A[M,Kd] @ W3[Kd,3] ---------
__global__ void k_gemv3(const float* __restrict__ A, const float* __restrict__ W3,
                        float* __restrict__ y, int M, int Kd) {
    int gw   = (blockIdx.x * blockDim.x + threadIdx.x) >> 5;
    int lane = threadIdx.x & 31;
    if (gw >= M) return;
    const float4* a4 = (const float4*)(A + (size_t)gw * Kd);
    float s0 = 0.f, s1 = 0.f, s2 = 0.f;
    for (int k4 = lane; k4 < Kd / 4; k4 += 32) {
        float4 av = a4[k4];
        int k = k4 * 4;
        s0 = fmaf(av.x, W3[k * 3 + 0], s0);
        s1 = fmaf(av.x, W3[k * 3 + 1], s1);
        s2 = fmaf(av.x, W3[k * 3 + 2], s2);
        s0 = fmaf(av.y, W3[k * 3 + 3], s0);
        s1 = fmaf(av.y, W3[k * 3 + 4], s1);
        s2 = fmaf(av.y, W3[k * 3 + 5], s2);
        s0 = fmaf(av.z, W3[k * 3 + 6], s0);
        s1 = fmaf(av.z, W3[k * 3 + 7], s1);
        s2 = fmaf(av.z, W3[k * 3 + 8], s2);
        s0 = fmaf(av.w, W3[k * 3 + 9], s0);
        s1 = fmaf(av.w, W3[k * 3 + 10], s1);
        s2 = fmaf(av.w, W3[k * 3 + 11], s2);
    }
    #pragma unroll
    for (int off = 16; off; off >>= 1) {
        s0 += __shfl_xor_sync(0xffffffffu, s0, off);
        s1 += __shfl_xor_sync(0xffffffffu, s1, off);
        s2 += __shfl_xor_sync(0xffffffffu, s2, off);
    }
    if (lane == 0) {
        y[(size_t)gw * 3 + 0] = s0;
        y[(size_t)gw * 3 + 1] = s1;
        y[(size_t)gw * 3 + 2] = s2;
    }
}

// ------------- epilogue: bias + dense + residual + fused relu (fp32 & fp16) --
__global__ void k_combine(const float* __restrict__ y, const float* __restrict__ cb,
                          const float* __restrict__ dw, const float* __restrict__ db,
                          const float* __restrict__ inp, int cin, int instride,
                          const float* __restrict__ xold, int xold_stride,
                          float* __restrict__ out, float* __restrict__ relu_out,
                          __half* __restrict__ hrelu_out,
                          int out_stride, int out_rows,
                          int conv_cols, int dense_cols, int dense_off, float scale) {
    __shared__ float si[96];
    int n = blockIdx.x;
    int o = threadIdx.x;  // 96
    if (o < cin) si[o] = inp[(size_t)n * instride + o];
    __syncthreads();
    int width = dense_off + dense_cols;
    if (conv_cols > width) width = conv_cols;
    if (o >= width || n >= out_rows) return;
    float v = 0.f;
    if (o < conv_cols) v = y[(size_t)n * conv_cols + o] + cb[o];
    if (o >= dense_off) {
        int od = o - dense_off;
        if (od < dense_cols) {
            float s2 = db[od];
            for (int i = 0; i < cin; i++) s2 = fmaf(si[i], dw[i * dense_cols + od], s2);
            v += s2;
        }
    }
    if (xold) v += xold[(size_t)n * xold_stride + o];
    v *= scale;
    out[(size_t)n * out_stride + o] = v;
    if (relu_out) {
        float r = fmaxf(v, 0.f);
        relu_out[(size_t)n * out_stride + o]  = r;
        hrelu_out[(size_t)n * out_stride + o] = __float2half(r);
    }
}

// ---------------- launch ----------------
extern "C" void kernel_launch(void* const* d_in, const int* in_sizes, int n_in,
                              void* d_out, int out_size) {
    const float* pos   = (const float*)d_in[0];
    const float* feats = (const float*)d_in[1];
    const int*   esrc  = (const int*)d_in[2];
    const int*   edst  = (const int*)d_in[3];
    const float* c0w = (const float*)d_in[4];
    const float* c0b = (const float*)d_in[5];
    const float* d0w = (const float*)d_in[6];
    const float* d0b = (const float*)d_in[7];
    const float* c1w = (const float*)d_in[8];
    const float* c1b = (const float*)d_in[9];
    const float* d1w = (const float*)d_in[10];
    const float* d1b = (const float*)d_in[11];
    const float* c2w = (const float*)d_in[12];
    const float* c2b = (const float*)d_in[13];
    const float* d2w = (const float*)d_in[14];
    const float* d2b = (const float*)d_in[15];
    const float* c3w = (const float*)d_in[16];
    const float* c3b = (const float*)d_in[17];
    const float* d3w = (const float*)d_in[18];
    const float* d3b = (const float*)d_in[19];
    float* out = (float*)d_out;

    void *pB, *pA, *pBB, *pI, *pI2, *pY, *pW0, *pH;
    cudaGetSymbolAddress(&pB,  g_B);
    cudaGetSymbolAddress(&pA,  g_bufA);
    cudaGetSymbolAddress(&pBB, g_bufB);
    cudaGetSymbolAddress(&pI,  g_inp);
    cudaGetSymbolAddress(&pI2, g_inp2);
    cudaGetSymbolAddress(&pY,  g_y);
    cudaGetSymbolAddress(&pW0, g_w0p);
    cudaGetSymbolAddress(&pH,  g_hf);
    float* B    = (float*)pB;
    float* bufA = (float*)pA;
    float* bufB = (float*)pBB;
    float* inp  = (float*)pI;
    float* inp2 = (float*)pI2;
    float* y    = (float*)pY;
    float* w0p  = (float*)pW0;
    __half* hf  = (__half*)pH;

    const int EB = (EPAD + 255) / 256;
    const int GT = (NN + 63) / 64;   // 313 GEMM M-tiles

    // preprocessing (shared across all 4 conv layers)
    k_pre<<<(NN * 16 + 255) / 256, 256>>>(feats, esrc, edst, inp, hf);   // (0)
    k_geom<<<EB, 256>>>(pos, esrc, edst);                                // (1)
    k_build<<<NN, 128>>>(edst);                                          // (2)

    // ---- layer 0 (cin 13 padded to 16) ----
    k_gather<16><<<NN, 128>>>(hf);                                       // (3) <- ncu slot
    k_padw0<<<(1024 * 64 + 255) / 256, 256>>>(c0w);
    k_cvtW<<<(1024 * 16 + 255) / 256, 256>>>(w0p, 1024 * 16);
    k_gemm_tf32<<<GT, 128>>>(B, y, NN, 64 * 16);
    k_combine<<<NN, 96>>>(y, c0b, d0w, d0b, inp, 13, 16, nullptr, 0,
                          bufA, inp2, hf, 96, NN, 64, 32, 64, 1.f);
    // ---- layer 1 ----
    k_gather<96><<<NN, 128>>>(hf);
    k_cvtW<<<(6144 * 16 + 255) / 256, 256>>>(c1w, 6144 * 16);
    k_gemm_tf32<<<GT, 128>>>(B, y, NN, 64 * 96);
    k_combine<<<NN, 96>>>(y, c1b, d1w, d1b, inp2, 96, 96, nullptr, 0,
                          bufB, inp, hf, 64, NN, 64, 64, 0, 1.f);
    // ---- layer 2 (residual) ----
    k_gather<64><<<NN, 128>>>(hf);
    k_cvtW<<<(4096 * 16 + 255) / 256, 256>>>(c2w, 4096 * 16);
    k_gemm_tf32<<<GT, 128>>>(B, y, NN, 64 * 64);
    k_combine<<<NN, 96>>>(y, c2b, d2w, d2b, inp, 64, 64, bufB, 64,
                          bufA, inp2, hf, 64, NN, 64, 64, 0, 1.f);
    // ---- layer 3 (output, /128, first 20000 rows) ----
    k_gather<64><<<NN, 128>>>(hf);
    k_gemv3<<<(NN * 32 + 255) / 256, 256>>>(B, c3w, y, NN, 64 * 64);
    k_combine<<<NREAL, 96>>>(y, c3b, d3w, d3b, inp2, 64, 64, nullptr, 0,
                             out, nullptr, nullptr, 3, NREAL, 3, 3, 0, 1.f / 128.f);
}